// round 1
// baseline (speedup 1.0000x reference)
#include <cuda_runtime.h>
#include <math.h>

#define NBATCH 64
#define HALF   512
#define INDIM  64
#define HID    256
#define EMB    128
#define MROWS  (NBATCH*HALF)   // 32768 unique rows
#define LN_EPS 1e-5f

#define GRAM_SMEM_BYTES (2*128*129*4)

// Scratch (device globals — allocation is forbidden)
__device__ float g_h [MROWS*HID];
__device__ float g_z [MROWS*EMB];
__device__ float g_sq[MROWS];
__device__ float g_s [MROWS];

__device__ __forceinline__ float warp_sum32(float v){
  #pragma unroll
  for (int o=16;o;o>>=1) v += __shfl_xor_sync(0xffffffffu, v, o);
  return v;
}

// ---------------------------------------------------------------------------
// Kernel 1: h = |H[li]-H[ri]| @ W_in + b_in   (32768 x 64 @ 64 x 256)
// Tile: 64 rows x 256 cols, 256 threads, 8x8 micro-tile per thread.
// ---------------------------------------------------------------------------
__global__ void __launch_bounds__(256) k_gemm_in(
    const float* __restrict__ H, const int* __restrict__ pairs,
    const float* __restrict__ W, const float* __restrict__ bias)
{
  __shared__ float a_sm[32][65];
  __shared__ float w_sm[32][HID];
  __shared__ int li_sm[64], ri_sm[64];
  const int tid = threadIdx.x;
  const int tx = tid & 31, ty = tid >> 5;
  const int row0 = blockIdx.x * 64;

  if (tid < 64) {
    li_sm[tid] = pairs[2*(row0+tid)];
    ri_sm[tid] = pairs[2*(row0+tid)+1];
  }
  __syncthreads();

  float acc[8][8];
  #pragma unroll
  for (int r=0;r<8;r++)
    #pragma unroll
    for (int i=0;i<8;i++) acc[r][i]=0.f;

  for (int c=0;c<INDIM;c+=32){
    #pragma unroll
    for (int e=tid;e<64*32;e+=256){
      int r=e>>5, kk=e&31;
      a_sm[kk][r] = fabsf(H[li_sm[r]*INDIM + c + kk] - H[ri_sm[r]*INDIM + c + kk]);
    }
    #pragma unroll
    for (int e=tid;e<32*HID;e+=256){
      int kk=e>>8, col=e&255;
      w_sm[kk][col] = W[(c+kk)*HID + col];
    }
    __syncthreads();
    #pragma unroll 8
    for (int kk=0;kk<32;kk++){
      float af[8], wf[8];
      #pragma unroll
      for (int r=0;r<8;r++) af[r]=a_sm[kk][ty*8+r];
      #pragma unroll
      for (int i=0;i<8;i++) wf[i]=w_sm[kk][tx+32*i];
      #pragma unroll
      for (int r=0;r<8;r++)
        #pragma unroll
        for (int i=0;i<8;i++) acc[r][i] = fmaf(af[r], wf[i], acc[r][i]);
    }
    __syncthreads();
  }
  #pragma unroll
  for (int r=0;r<8;r++){
    int row = row0 + ty*8 + r;
    #pragma unroll
    for (int i=0;i<8;i++){
      int col = tx + 32*i;
      g_h[row*HID + col] = acc[r][i] + bias[col];
    }
  }
}

// ---------------------------------------------------------------------------
// Kernel 2: one residual block, fully fused (in place on g_h):
//   h = h + relu( LN(h @ Wb + bb, g, b) )
// LN over 256 cols done with warp shuffles (a warp owns 8 full rows).
// ---------------------------------------------------------------------------
__global__ void __launch_bounds__(256) k_block(
    const float* __restrict__ W, const float* __restrict__ bias,
    const float* __restrict__ lg, const float* __restrict__ lb)
{
  __shared__ float a_sm[32][65];
  __shared__ float w_sm[32][HID];
  const int tid=threadIdx.x, tx=tid&31, ty=tid>>5;
  const int row0 = blockIdx.x*64;

  float acc[8][8];
  #pragma unroll
  for (int r=0;r<8;r++)
    #pragma unroll
    for (int i=0;i<8;i++) acc[r][i]=0.f;

  for (int c=0;c<HID;c+=32){
    #pragma unroll
    for (int e=tid;e<64*32;e+=256){
      int r=e>>5, kk=e&31;
      a_sm[kk][r] = g_h[(row0+r)*HID + c + kk];
    }
    #pragma unroll
    for (int e=tid;e<32*HID;e+=256){
      int kk=e>>8, col=e&255;
      w_sm[kk][col] = W[(c+kk)*HID + col];
    }
    __syncthreads();
    #pragma unroll 8
    for (int kk=0;kk<32;kk++){
      float af[8], wf[8];
      #pragma unroll
      for (int r=0;r<8;r++) af[r]=a_sm[kk][ty*8+r];
      #pragma unroll
      for (int i=0;i<8;i++) wf[i]=w_sm[kk][tx+32*i];
      #pragma unroll
      for (int r=0;r<8;r++)
        #pragma unroll
        for (int i=0;i<8;i++) acc[r][i] = fmaf(af[r], wf[i], acc[r][i]);
    }
    __syncthreads();
  }

  #pragma unroll
  for (int r=0;r<8;r++){
    int row = row0 + ty*8 + r;
    float v[8]; float s1=0.f;
    #pragma unroll
    for (int i=0;i<8;i++){ v[i]=acc[r][i]+bias[tx+32*i]; s1+=v[i]; }
    s1 = warp_sum32(s1);
    float mu = s1*(1.f/HID);
    float s2=0.f;
    #pragma unroll
    for (int i=0;i<8;i++){ float d=v[i]-mu; s2 += d*d; }
    s2 = warp_sum32(s2);
    float rs = rsqrtf(s2*(1.f/HID)+LN_EPS);
    #pragma unroll
    for (int i=0;i<8;i++){
      int col = tx+32*i;
      float t = (v[i]-mu)*rs*lg[col]+lb[col];
      t = fmaxf(t, 0.f);
      g_h[row*HID+col] += t;
    }
  }
}

// ---------------------------------------------------------------------------
// Kernel 3: z = LN(h @ W_out + b_out)  (EMB=128), also sq[row] = sum z^2
// ---------------------------------------------------------------------------
__global__ void __launch_bounds__(256) k_out(
    const float* __restrict__ W, const float* __restrict__ bias,
    const float* __restrict__ lg, const float* __restrict__ lb)
{
  __shared__ float a_sm[32][65];
  __shared__ float w_sm[32][EMB];
  const int tid=threadIdx.x, tx=tid&31, ty=tid>>5;
  const int row0 = blockIdx.x*64;

  float acc[8][4];
  #pragma unroll
  for (int r=0;r<8;r++)
    #pragma unroll
    for (int i=0;i<4;i++) acc[r][i]=0.f;

  for (int c=0;c<HID;c+=32){
    #pragma unroll
    for (int e=tid;e<64*32;e+=256){
      int r=e>>5, kk=e&31;
      a_sm[kk][r] = g_h[(row0+r)*HID + c + kk];
    }
    #pragma unroll
    for (int e=tid;e<32*EMB;e+=256){
      int kk=e>>7, col=e&127;
      w_sm[kk][col] = W[(c+kk)*EMB + col];
    }
    __syncthreads();
    #pragma unroll 8
    for (int kk=0;kk<32;kk++){
      float af[8], wf[4];
      #pragma unroll
      for (int r=0;r<8;r++) af[r]=a_sm[kk][ty*8+r];
      #pragma unroll
      for (int i=0;i<4;i++) wf[i]=w_sm[kk][tx+32*i];
      #pragma unroll
      for (int r=0;r<8;r++)
        #pragma unroll
        for (int i=0;i<4;i++) acc[r][i] = fmaf(af[r], wf[i], acc[r][i]);
    }
    __syncthreads();
  }

  #pragma unroll
  for (int r=0;r<8;r++){
    int row = row0 + ty*8 + r;
    float v[4]; float s1=0.f;
    #pragma unroll
    for (int i=0;i<4;i++){ v[i]=acc[r][i]+bias[tx+32*i]; s1+=v[i]; }
    s1 = warp_sum32(s1);
    float mu = s1*(1.f/EMB);
    float s2=0.f;
    #pragma unroll
    for (int i=0;i<4;i++){ float d=v[i]-mu; s2 += d*d; }
    s2 = warp_sum32(s2);
    float rs = rsqrtf(s2*(1.f/EMB)+LN_EPS);
    float qs = 0.f;
    #pragma unroll
    for (int i=0;i<4;i++){
      int col = tx+32*i;
      float t = (v[i]-mu)*rs*lg[col]+lb[col];
      g_z[row*EMB+col] = t;
      qs += t*t;
    }
    qs = warp_sum32(qs);
    if (tx==0) g_sq[row] = qs;
  }
}

// ---------------------------------------------------------------------------
// Kernel 4: per-batch gram on UNIQUE rows (512x512, K=128) fused with
// dist = sqrt(max(sq_r + sq_c - 2*dot, 1e-12)) and row-sum into g_s.
// Grid (4 row-tiles, 64 batches). 132KB dynamic smem, 8x8 micro-tiles.
// ---------------------------------------------------------------------------
extern __shared__ float dynsm[];
__global__ void __launch_bounds__(256) k_gram()
{
  float* zr = dynsm;              // [128][129] rows tile
  float* zc = dynsm + 128*129;    // [128][129] cols tile
  const int tid=threadIdx.x, tx2=tid&15, ty2=tid>>4;
  const int bofs = blockIdx.y * HALF;
  const int p0 = bofs + blockIdx.x * 128;

  #pragma unroll
  for (int e=tid;e<128*EMB;e+=256){
    int r=e>>7, k=e&127;
    zr[r*129+k] = g_z[(p0+r)*EMB+k];
  }
  const int rbase = ty2*8;
  float sqr[8], rowsum[8];
  #pragma unroll
  for (int r=0;r<8;r++){ sqr[r]=g_sq[p0+rbase+r]; rowsum[r]=0.f; }

  for (int cb=0; cb<HALF; cb+=128){
    __syncthreads();
    #pragma unroll
    for (int e=tid;e<128*EMB;e+=256){
      int r=e>>7, k=e&127;
      zc[r*129+k] = g_z[(bofs+cb+r)*EMB+k];
    }
    __syncthreads();

    float acc[8][8];
    #pragma unroll
    for (int r=0;r<8;r++)
      #pragma unroll
      for (int c=0;c<8;c++) acc[r][c]=0.f;

    #pragma unroll 4
    for (int k=0;k<EMB;k++){
      float af[8], bf[8];
      #pragma unroll
      for (int r=0;r<8;r++) af[r]=zr[(rbase+r)*129+k];
      #pragma unroll
      for (int c=0;c<8;c++) bf[c]=zc[(tx2+16*c)*129+k];
      #pragma unroll
      for (int r=0;r<8;r++)
        #pragma unroll
        for (int c=0;c<8;c++) acc[r][c] = fmaf(af[r], bf[c], acc[r][c]);
    }
    #pragma unroll
    for (int c=0;c<8;c++){
      float sqc = g_sq[bofs+cb+tx2+16*c];
      #pragma unroll
      for (int r=0;r<8;r++){
        float d2 = sqr[r] + sqc - 2.f*acc[r][c];
        rowsum[r] += sqrtf(fmaxf(d2, 1e-12f));
      }
    }
  }
  #pragma unroll
  for (int r=0;r<8;r++){
    float v = rowsum[r];
    #pragma unroll
    for (int o=8;o;o>>=1) v += __shfl_xor_sync(0xffffffffu, v, o, 16);
    if (tx2==0) g_s[p0+rbase+r] = v;
  }
}

// ---------------------------------------------------------------------------
// Kernel 5: per batch: softmax over 512 unique scores (full-1024 softmax
// equals unique/2 per duplicate), write w (both halves), f = sum(su * z).
// ---------------------------------------------------------------------------
__global__ void __launch_bounds__(256) k_final(
    const int* __restrict__ pairs, float* __restrict__ out)
{
  __shared__ float ev[512];
  __shared__ float red[256];
  const int b = blockIdx.x, tid = threadIdx.x;
  // s = rowsum/512 (mean over 1024 duplicated cols); x = s / TAU (=0.25)
  const float scale = 1.f/(512.f*0.25f);
  float x0 = g_s[b*HALF + tid      ]*scale;
  float x1 = g_s[b*HALF + 256 + tid]*scale;

  red[tid] = fmaxf(x0,x1);
  __syncthreads();
  for (int o=128;o;o>>=1){ if(tid<o) red[tid]=fmaxf(red[tid],red[tid+o]); __syncthreads(); }
  float mx = red[0];
  __syncthreads();

  float e0 = expf(x0-mx), e1 = expf(x1-mx);
  ev[tid] = e0; ev[tid+256] = e1;
  red[tid] = e0+e1;
  __syncthreads();
  for (int o=128;o;o>>=1){ if(tid<o) red[tid]+=red[tid+o]; __syncthreads(); }
  float inv = 1.f/red[0];

  // w output: full softmax weight = (unique softmax)/2 at both li and ri
  float* wout = out + NBATCH*EMB;
  {
    int p = b*HALF + tid;
    float wv = ev[tid]*inv*0.5f;
    wout[pairs[2*p]]   = wv;
    wout[pairs[2*p+1]] = wv;
    p = b*HALF + 256 + tid;
    wv = ev[tid+256]*inv*0.5f;
    wout[pairs[2*p]]   = wv;
    wout[pairs[2*p+1]] = wv;
  }

  // f[b] = sum over unique rows of (unique softmax) * z
  const int col = tid & 127, part = tid >> 7;
  float fs = 0.f;
  for (int i = part*256; i < part*256+256; i++)
    fs += ev[i]*inv * g_z[(b*HALF+i)*EMB + col];
  __syncthreads();
  red[tid] = fs;
  __syncthreads();
  if (tid < 128) out[b*EMB + tid] = red[tid] + red[tid+128];
}

// ---------------------------------------------------------------------------
extern "C" void kernel_launch(void* const* d_in, const int* in_sizes, int n_in,
                              void* d_out, int out_size)
{
  const float* H     = (const float*)d_in[0];
  // d_in[1] = batch_ptr (structure implied, unused)
  const int*   pairs = (const int*)  d_in[2];
  const float* W_in  = (const float*)d_in[3];
  const float* b_in  = (const float*)d_in[4];
  const float* Wb    = (const float*)d_in[5];
  const float* bb    = (const float*)d_in[6];
  const float* lng   = (const float*)d_in[7];
  const float* lnb   = (const float*)d_in[8];
  const float* W_out = (const float*)d_in[9];
  const float* b_out = (const float*)d_in[10];
  const float* lnf_g = (const float*)d_in[11];
  const float* lnf_b = (const float*)d_in[12];
  float* out = (float*)d_out;

  cudaFuncSetAttribute(k_gram, cudaFuncAttributeMaxDynamicSharedMemorySize,
                       GRAM_SMEM_BYTES);

  k_gemm_in<<<MROWS/64, 256>>>(H, pairs, W_in, b_in);
  for (int k=0;k<3;k++)
    k_block<<<MROWS/64, 256>>>(Wb + (size_t)k*HID*HID, bb + (size_t)k*HID,
                               lng + (size_t)k*HID, lnb + (size_t)k*HID);
  k_out<<<MROWS/64, 256>>>(W_out, b_out, lnf_g, lnf_b);
  k_gram<<<dim3(4, NBATCH), 256, GRAM_SMEM_BYTES>>>();
  k_final<<<NBATCH, 256>>>(pairs, out);
}

// round 3
// speedup vs baseline: 1.7914x; 1.7914x over previous
#include <cuda_runtime.h>
#include <cuda_bf16.h>
#include <math.h>
#include <stdint.h>

#define NBATCH 64
#define HALF   512
#define INDIM  64
#define HID    256
#define EMB    128
#define MROWS  (NBATCH*HALF)   // 32768 unique rows
#define LN_EPS 1e-5f

// ---------------- device scratch (allocation is forbidden) ------------------
__device__ __align__(16) __nv_bfloat16 g_ah[MROWS*HID];   // h hi
__device__ __align__(16) __nv_bfloat16 g_al[MROWS*HID];   // h lo
__device__ __align__(16) __nv_bfloat16 g_bt_hi[3*HID*HID + EMB*HID]; // W^T hi
__device__ __align__(16) __nv_bfloat16 g_bt_lo[3*HID*HID + EMB*HID]; // W^T lo
__device__ __align__(16) float g_z [MROWS*EMB];
__device__ float g_sq[MROWS];
__device__ float g_s [MROWS];

// ---------------- helpers ----------------------------------------------------
__device__ __forceinline__ uint32_t smem_u32(const void* p){
  uint32_t a;
  asm("{ .reg .u64 t; cvta.to.shared.u64 t, %1; cvt.u32.u64 %0, t; }" : "=r"(a) : "l"(p));
  return a;
}
__device__ __forceinline__ float warp_sum32(float v){
  #pragma unroll
  for (int o=16;o;o>>=1) v += __shfl_xor_sync(0xffffffffu, v, o);
  return v;
}
__device__ __forceinline__ void cp16(uint32_t dst, const void* src){
  asm volatile("cp.async.cg.shared.global [%0], [%1], 16;\n" :: "r"(dst), "l"(src));
}
#define CP_COMMIT() asm volatile("cp.async.commit_group;\n" ::: "memory")
#define CP_WAIT(n)  asm volatile("cp.async.wait_group %0;\n" :: "n"(n) : "memory")

__device__ __forceinline__ void ldsm4(uint32_t (&r)[4], uint32_t addr){
  asm volatile("ldmatrix.sync.aligned.m8n8.x4.shared.b16 {%0,%1,%2,%3}, [%4];\n"
    : "=r"(r[0]),"=r"(r[1]),"=r"(r[2]),"=r"(r[3]) : "r"(addr));
}
__device__ __forceinline__ void mma16816(float (&d)[4], const uint32_t (&a)[4],
                                         uint32_t b0, uint32_t b1){
  asm volatile("mma.sync.aligned.m16n8k16.row.col.f32.bf16.bf16.f32 "
    "{%0,%1,%2,%3}, {%4,%5,%6,%7}, {%8,%9}, {%0,%1,%2,%3};\n"
    : "+f"(d[0]),"+f"(d[1]),"+f"(d[2]),"+f"(d[3])
    : "r"(a[0]),"r"(a[1]),"r"(a[2]),"r"(a[3]), "r"(b0),"r"(b1));
}
// rows of 64B (32 bf16); chunk c in 0..3; XOR swizzle for conflict-free LDSM
__device__ __forceinline__ uint32_t swz(int r, int c){
  return (uint32_t)(r*64 + ((c ^ ((r>>1)&3))<<4));
}
__device__ __forceinline__ void split_bf16(float x, __nv_bfloat16& h, __nv_bfloat16& l){
  h = __float2bfloat16(x);
  l = __float2bfloat16(x - __bfloat162float(h));
}

// shared warp-tile: 32 rows x 64 cols, one k32 chunk, bf16x3 accumulate
__device__ __forceinline__ void warp_mma_chunk(
    float (&acc)[2][8][4],
    uint32_t aH, uint32_t aL, uint32_t bH, uint32_t bL,
    int wm, int wn, int lane)
{
  #pragma unroll
  for (int kk=0; kk<2; kk++){
    uint32_t ah[2][4], al[2][4];
    #pragma unroll
    for (int mi=0; mi<2; mi++){
      int row = wm*32 + mi*16 + (lane & 15);
      int c   = kk*2 + (lane >> 4);
      uint32_t off = swz(row, c);
      ldsm4(ah[mi], aH + off);
      ldsm4(al[mi], aL + off);
    }
    #pragma unroll
    for (int p=0; p<4; p++){
      int n = wn*64 + p*16 + ((lane>>4)<<3) + (lane & 7);
      int c = kk*2 + ((lane>>3)&1);
      uint32_t off = swz(n, c);
      uint32_t bh[4], bl[4];
      ldsm4(bh, bH + off);
      ldsm4(bl, bL + off);
      #pragma unroll
      for (int mi=0; mi<2; mi++){
        #pragma unroll
        for (int h=0; h<2; h++){
          mma16816(acc[mi][p*2+h], ah[mi], bh[2*h], bh[2*h+1]);
          mma16816(acc[mi][p*2+h], ah[mi], bl[2*h], bl[2*h+1]);
          mma16816(acc[mi][p*2+h], al[mi], bh[2*h], bh[2*h+1]);
        }
      }
    }
  }
}

// ---------------------------------------------------------------------------
// prep: transpose + hi/lo split of block weights and W_out into [n][k] layout
// ---------------------------------------------------------------------------
__global__ void __launch_bounds__(256) k_prep(
    const float* __restrict__ Wb, const float* __restrict__ Wout)
{
  int i = blockIdx.x*256 + threadIdx.x;
  float v;
  if (i < 3*HID*HID){
    int layer = i >> 16;
    int n  = (i >> 8) & 255;
    int kk = i & 255;
    v = Wb[layer*HID*HID + kk*HID + n];
  } else if (i < 3*HID*HID + EMB*HID){
    int j = i - 3*HID*HID;
    int n  = j >> 8;
    int kk = j & 255;
    v = Wout[kk*EMB + n];
  } else return;
  __nv_bfloat16 h, l; split_bf16(v, h, l);
  g_bt_hi[i] = h; g_bt_lo[i] = l;
}

// ---------------------------------------------------------------------------
// k_gemm_in (SIMT): h = |H[li]-H[ri]| @ W_in + b_in  -> g_ah/g_al (bf16 pair)
// ---------------------------------------------------------------------------
__global__ void __launch_bounds__(256) k_gemm_in(
    const float* __restrict__ H, const int* __restrict__ pairs,
    const float* __restrict__ W, const float* __restrict__ bias)
{
  __shared__ float a_sm[32][65];
  __shared__ float w_sm[32][HID];
  __shared__ int li_sm[64], ri_sm[64];
  const int tid = threadIdx.x;
  const int tx = tid & 31, ty = tid >> 5;
  const int row0 = blockIdx.x * 64;

  if (tid < 64) {
    li_sm[tid] = pairs[2*(row0+tid)];
    ri_sm[tid] = pairs[2*(row0+tid)+1];
  }
  __syncthreads();

  float acc[8][8];
  #pragma unroll
  for (int r=0;r<8;r++)
    #pragma unroll
    for (int i=0;i<8;i++) acc[r][i]=0.f;

  for (int c=0;c<INDIM;c+=32){
    #pragma unroll
    for (int e=tid;e<64*32;e+=256){
      int r=e>>5, kk=e&31;
      a_sm[kk][r] = fabsf(H[li_sm[r]*INDIM + c + kk] - H[ri_sm[r]*INDIM + c + kk]);
    }
    #pragma unroll
    for (int e=tid;e<32*HID;e+=256){
      int kk=e>>8, col=e&255;
      w_sm[kk][col] = W[(c+kk)*HID + col];
    }
    __syncthreads();
    #pragma unroll 8
    for (int kk=0;kk<32;kk++){
      float af[8], wf[8];
      #pragma unroll
      for (int r=0;r<8;r++) af[r]=a_sm[kk][ty*8+r];
      #pragma unroll
      for (int i=0;i<8;i++) wf[i]=w_sm[kk][tx+32*i];
      #pragma unroll
      for (int r=0;r<8;r++)
        #pragma unroll
        for (int i=0;i<8;i++) acc[r][i] = fmaf(af[r], wf[i], acc[r][i]);
    }
    __syncthreads();
  }
  #pragma unroll
  for (int r=0;r<8;r++){
    int row = row0 + ty*8 + r;
    #pragma unroll
    for (int i=0;i<8;i++){
      int col = tx + 32*i;
      float v = acc[r][i] + bias[col];
      __nv_bfloat16 h, l; split_bf16(v, h, l);
      g_ah[(size_t)row*HID + col] = h;
      g_al[(size_t)row*HID + col] = l;
    }
  }
}

// ---------------------------------------------------------------------------
// k_block_mma: h = h + relu(LN(h @ Wb + bb))  via mma.sync bf16x3
// CTA: 64 rows x 256 cols, 8 warps (2M x 4N), K=256 in 8 chunks of 32.
// SMEM stage s at s*40960: A_hi[0,4K) A_lo[4K,8K) B_hi[8K,24K) B_lo[24K,40K)
// ---------------------------------------------------------------------------
#define BLK_STAGE 40960
#define BLK_SMEM  (81920 + 3072)
__global__ void __launch_bounds__(256) k_block_mma(
    int layer, const float* __restrict__ bb,
    const float* __restrict__ lg, const float* __restrict__ lb)
{
  extern __shared__ char smem[];
  const uint32_t sb = smem_u32(smem);
  const int tid = threadIdx.x, lane = tid&31, wid = tid>>5;
  const int wm = wid>>2, wn = wid&3;
  const int row0 = blockIdx.x * 64;
  const __nv_bfloat16* __restrict__ WtHi = g_bt_hi + (size_t)layer*HID*HID;
  const __nv_bfloat16* __restrict__ WtLo = g_bt_lo + (size_t)layer*HID*HID;

  float* prm = (float*)(smem + 81920);
  prm[tid] = bb[tid]; prm[256+tid] = lg[tid]; prm[512+tid] = lb[tid];

  // chunk loader (all 256 threads)
  const int ar = tid>>2, aq = tid&3;
  auto load_chunk = [&](int c, int buf){
    uint32_t base = sb + (uint32_t)buf*BLK_STAGE;
    int kc = c*32;
    {
      size_t gi = (size_t)(row0+ar)*HID + kc + aq*8;
      uint32_t off = swz(ar, aq);
      cp16(base + off,        g_ah + gi);
      cp16(base + 4096 + off, g_al + gi);
    }
    #pragma unroll
    for (int u=0; u<4; u++){
      int e = tid + u*256;
      int n = e>>2, q = e&3;
      size_t gi = (size_t)n*HID + kc + q*8;
      uint32_t off = swz(n, q);
      cp16(base + 8192  + off, WtHi + gi);
      cp16(base + 24576 + off, WtLo + gi);
    }
    CP_COMMIT();
  };

  float acc[2][8][4];
  #pragma unroll
  for (int mi=0;mi<2;mi++)
    #pragma unroll
    for (int j=0;j<8;j++)
      #pragma unroll
      for (int q=0;q<4;q++) acc[mi][j][q]=0.f;

  load_chunk(0,0);
  load_chunk(1,1);
  for (int c=0;c<8;c++){
    if (c<6) { CP_WAIT(1); } else { CP_WAIT(0); }
    __syncthreads();
    uint32_t base = sb + (uint32_t)(c&1)*BLK_STAGE;
    warp_mma_chunk(acc, base, base+4096, base+8192, base+24576, wm, wn, lane);
    __syncthreads();
    if (c<6) load_chunk(c+2, c&1);
  }

  // epilogue: stage accums in smem (overlaps dead stage buffers)
  float* res = (float*)smem;   // [64][264]
  #pragma unroll
  for (int mi=0;mi<2;mi++){
    int r0r = wm*32 + mi*16 + (lane>>2);
    #pragma unroll
    for (int j=0;j<8;j++){
      int col = wn*64 + j*8 + 2*(lane&3);
      res[r0r*264+col]       = acc[mi][j][0];
      res[r0r*264+col+1]     = acc[mi][j][1];
      res[(r0r+8)*264+col]   = acc[mi][j][2];
      res[(r0r+8)*264+col+1] = acc[mi][j][3];
    }
  }
  __syncthreads();

  // LN + relu: warp w handles rows 8w..8w+7, lanes split the 256 cols
  #pragma unroll
  for (int r8=0;r8<8;r8++){
    int row = wid*8 + r8;
    float v[8]; float s1=0.f;
    #pragma unroll
    for (int i=0;i<8;i++){ v[i]=res[row*264 + lane + 32*i] + prm[lane+32*i]; s1+=v[i]; }
    s1 = warp_sum32(s1);
    float mu = s1*(1.f/256.f);
    float s2=0.f;
    #pragma unroll
    for (int i=0;i<8;i++){ float d=v[i]-mu; s2+=d*d; }
    s2 = warp_sum32(s2);
    float rs = rsqrtf(s2*(1.f/256.f)+LN_EPS);
    #pragma unroll
    for (int i=0;i<8;i++){
      int cc = lane+32*i;
      float t = (v[i]-mu)*rs*prm[256+cc] + prm[512+cc];
      res[row*264+cc] = fmaxf(t, 0.f);
    }
  }
  __syncthreads();

  // residual add + bf16-pair writeback
  for (int u=tid; u<2048; u+=256){
    int r = u>>5, q = u&31;
    float v[8];
    *(float4*)v     = *(float4*)(res + r*264 + q*8);
    *(float4*)(v+4) = *(float4*)(res + r*264 + q*8 + 4);
    size_t gi = (size_t)(row0+r)*HID + q*8;
    uint4 hh = *(const uint4*)(g_ah + gi);
    uint4 ll = *(const uint4*)(g_al + gi);
    const __nv_bfloat16* hp = (const __nv_bfloat16*)&hh;
    const __nv_bfloat16* lp = (const __nv_bfloat16*)&ll;
    __nv_bfloat16 oh[8], ol[8];
    #pragma unroll
    for (int i=0;i<8;i++){
      float x = __bfloat162float(hp[i]) + __bfloat162float(lp[i]) + v[i];
      split_bf16(x, oh[i], ol[i]);
    }
    *(uint4*)(g_ah + gi) = *(uint4*)oh;
    *(uint4*)(g_al + gi) = *(uint4*)ol;
  }
}

// ---------------------------------------------------------------------------
// k_out_mma: z = LN(h @ W_out + b_out), sq = sum z^2  (mma.sync bf16x3)
// CTA: 128 rows x 128 cols, 8 warps (4M x 2N).
// Stage s at s*32768: A_hi[0,8K) A_lo[8K,16K) B_hi[16K,24K) B_lo[24K,32K)
// ---------------------------------------------------------------------------
#define OUT_STAGE 32768
#define OUT_SMEM  (69632 + 1536)
__global__ void __launch_bounds__(256) k_out_mma(
    const float* __restrict__ bo, const float* __restrict__ lg,
    const float* __restrict__ lb)
{
  extern __shared__ char smem[];
  const uint32_t sb = smem_u32(smem);
  const int tid = threadIdx.x, lane = tid&31, wid = tid>>5;
  const int wm = wid>>1, wn = wid&1;
  const int row0 = blockIdx.x * 128;
  const __nv_bfloat16* __restrict__ WtHi = g_bt_hi + 3*HID*HID;
  const __nv_bfloat16* __restrict__ WtLo = g_bt_lo + 3*HID*HID;

  float* prm = (float*)(smem + 69632);
  if (tid < 128){ prm[tid]=bo[tid]; prm[128+tid]=lg[tid]; prm[256+tid]=lb[tid]; }

  auto load_chunk = [&](int c, int buf){
    uint32_t base = sb + (uint32_t)buf*OUT_STAGE;
    int kc = c*32;
    #pragma unroll
    for (int u=0; u<2; u++){
      int e = tid + u*256;
      int r = e>>2, q = e&3;
      size_t gi = (size_t)(row0+r)*HID + kc + q*8;
      uint32_t off = swz(r, q);
      cp16(base + off,        g_ah + gi);
      cp16(base + 8192 + off, g_al + gi);
    }
    #pragma unroll
    for (int u=0; u<2; u++){
      int e = tid + u*256;
      int n = e>>2, q = e&3;
      size_t gi = (size_t)n*HID + kc + q*8;
      uint32_t off = swz(n, q);
      cp16(base + 16384 + off, WtHi + gi);
      cp16(base + 24576 + off, WtLo + gi);
    }
    CP_COMMIT();
  };

  float acc[2][8][4];
  #pragma unroll
  for (int mi=0;mi<2;mi++)
    #pragma unroll
    for (int j=0;j<8;j++)
      #pragma unroll
      for (int q=0;q<4;q++) acc[mi][j][q]=0.f;

  load_chunk(0,0);
  load_chunk(1,1);
  for (int c=0;c<8;c++){
    if (c<6) { CP_WAIT(1); } else { CP_WAIT(0); }
    __syncthreads();
    uint32_t base = sb + (uint32_t)(c&1)*OUT_STAGE;
    warp_mma_chunk(acc, base, base+8192, base+16384, base+24576, wm, wn, lane);
    __syncthreads();
    if (c<6) load_chunk(c+2, c&1);
  }

  float* res = (float*)smem;   // [128][136]
  #pragma unroll
  for (int mi=0;mi<2;mi++){
    int r0r = wm*32 + mi*16 + (lane>>2);
    #pragma unroll
    for (int j=0;j<8;j++){
      int col = wn*64 + j*8 + 2*(lane&3);
      res[r0r*136+col]       = acc[mi][j][0];
      res[r0r*136+col+1]     = acc[mi][j][1];
      res[(r0r+8)*136+col]   = acc[mi][j][2];
      res[(r0r+8)*136+col+1] = acc[mi][j][3];
    }
  }
  __syncthreads();

  // LN over 128 cols: warp w handles rows 16w..16w+15, 4 cols/lane
  #pragma unroll
  for (int r16=0;r16<16;r16++){
    int row = wid*16 + r16;
    float v[4]; float s1=0.f;
    #pragma unroll
    for (int i=0;i<4;i++){ v[i]=res[row*136 + lane + 32*i] + prm[lane+32*i]; s1+=v[i]; }
    s1 = warp_sum32(s1);
    float mu = s1*(1.f/128.f);
    float s2=0.f;
    #pragma unroll
    for (int i=0;i<4;i++){ float d=v[i]-mu; s2+=d*d; }
    s2 = warp_sum32(s2);
    float rs = rsqrtf(s2*(1.f/128.f)+LN_EPS);
    float qs=0.f;
    #pragma unroll
    for (int i=0;i<4;i++){
      int cc = lane+32*i;
      float t = (v[i]-mu)*rs*prm[128+cc] + prm[256+cc];
      res[row*136+cc] = t;
      qs += t*t;
    }
    qs = warp_sum32(qs);
    if (lane==0) g_sq[row0+row] = qs;
  }
  __syncthreads();

  for (int u=tid; u<4096; u+=256){
    int r = u>>5, q = u&31;
    float4 a = *(float4*)(res + r*136 + q*4);
    *(float4*)(g_z + (size_t)(row0+r)*EMB + q*4) = a;
  }
}

// ---------------------------------------------------------------------------
// k_gram: per-batch 512x512 pairwise distances on unique rows, row-sum -> g_s
// ---------------------------------------------------------------------------
#define GRAM_SMEM_BYTES (2*128*129*4)
__global__ void __launch_bounds__(256) k_gram()
{
  extern __shared__ char smem[];
  float* dynsm = (float*)smem;
  float* zr = dynsm;
  float* zc = dynsm + 128*129;
  const int tid=threadIdx.x, tx2=tid&15, ty2=tid>>4;
  const int bofs = blockIdx.y * HALF;
  const int p0 = bofs + blockIdx.x * 128;

  #pragma unroll
  for (int e=tid;e<128*EMB;e+=256){
    int r=e>>7, k=e&127;
    zr[r*129+k] = g_z[(size_t)(p0+r)*EMB+k];
  }
  const int rbase = ty2*8;
  float sqr[8], rowsum[8];
  #pragma unroll
  for (int r=0;r<8;r++){ sqr[r]=g_sq[p0+rbase+r]; rowsum[r]=0.f; }

  for (int cb=0; cb<HALF; cb+=128){
    __syncthreads();
    #pragma unroll
    for (int e=tid;e<128*EMB;e+=256){
      int r=e>>7, k=e&127;
      zc[r*129+k] = g_z[(size_t)(bofs+cb+r)*EMB+k];
    }
    __syncthreads();

    float acc[8][8];
    #pragma unroll
    for (int r=0;r<8;r++)
      #pragma unroll
      for (int c=0;c<8;c++) acc[r][c]=0.f;

    #pragma unroll 4
    for (int k=0;k<EMB;k++){
      float af[8], bf[8];
      #pragma unroll
      for (int r=0;r<8;r++) af[r]=zr[(rbase+r)*129+k];
      #pragma unroll
      for (int c=0;c<8;c++) bf[c]=zc[(tx2+16*c)*129+k];
      #pragma unroll
      for (int r=0;r<8;r++)
        #pragma unroll
        for (int c=0;c<8;c++) acc[r][c] = fmaf(af[r], bf[c], acc[r][c]);
    }
    #pragma unroll
    for (int c=0;c<8;c++){
      float sqc = g_sq[bofs+cb+tx2+16*c];
      #pragma unroll
      for (int r=0;r<8;r++){
        float d2 = sqr[r] + sqc - 2.f*acc[r][c];
        rowsum[r] += sqrtf(fmaxf(d2, 1e-12f));
      }
    }
  }
  #pragma unroll
  for (int r=0;r<8;r++){
    float v = rowsum[r];
    #pragma unroll
    for (int o=8;o;o>>=1) v += __shfl_xor_sync(0xffffffffu, v, o, 16);
    if (tx2==0) g_s[p0+rbase+r] = v;
  }
}

// ---------------------------------------------------------------------------
// k_final: softmax over 512 unique scores + weighted sum; write w and f.
// ---------------------------------------------------------------------------
__global__ void __launch_bounds__(256) k_final(
    const int* __restrict__ pairs, float* __restrict__ out)
{
  __shared__ float ev[512];
  __shared__ float red[256];
  const int b = blockIdx.x, tid = threadIdx.x;
  const float scale = 1.f/(512.f*0.25f);
  float x0 = g_s[b*HALF + tid      ]*scale;
  float x1 = g_s[b*HALF + 256 + tid]*scale;

  red[tid] = fmaxf(x0,x1);
  __syncthreads();
  for (int o=128;o;o>>=1){ if(tid<o) red[tid]=fmaxf(red[tid],red[tid+o]); __syncthreads(); }
  float mx = red[0];
  __syncthreads();

  float e0 = expf(x0-mx), e1 = expf(x1-mx);
  ev[tid] = e0; ev[tid+256] = e1;
  red[tid] = e0+e1;
  __syncthreads();
  for (int o=128;o;o>>=1){ if(tid<o) red[tid]+=red[tid+o]; __syncthreads(); }
  float inv = 1.f/red[0];

  float* wout = out + NBATCH*EMB;
  {
    int p = b*HALF + tid;
    float wv = ev[tid]*inv*0.5f;
    wout[pairs[2*p]]   = wv;
    wout[pairs[2*p+1]] = wv;
    p = b*HALF + 256 + tid;
    wv = ev[tid+256]*inv*0.5f;
    wout[pairs[2*p]]   = wv;
    wout[pairs[2*p+1]] = wv;
  }

  const int col = tid & 127, part = tid >> 7;
  float fs = 0.f;
  for (int i = part*256; i < part*256+256; i++)
    fs += ev[i]*inv * g_z[(size_t)(b*HALF+i)*EMB + col];
  __syncthreads();
  red[tid] = fs;
  __syncthreads();
  if (tid < 128) out[b*EMB + tid] = red[tid] + red[tid+128];
}

// ---------------------------------------------------------------------------
extern "C" void kernel_launch(void* const* d_in, const int* in_sizes, int n_in,
                              void* d_out, int out_size)
{
  const float* H     = (const float*)d_in[0];
  const int*   pairs = (const int*)  d_in[2];
  const float* W_in  = (const float*)d_in[3];
  const float* b_in  = (const float*)d_in[4];
  const float* Wb    = (const float*)d_in[5];
  const float* bb    = (const float*)d_in[6];
  const float* lng   = (const float*)d_in[7];
  const float* lnb   = (const float*)d_in[8];
  const float* W_out = (const float*)d_in[9];
  const float* b_out = (const float*)d_in[10];
  const float* lnf_g = (const float*)d_in[11];
  const float* lnf_b = (const float*)d_in[12];
  float* out = (float*)d_out;

  cudaFuncSetAttribute(k_block_mma, cudaFuncAttributeMaxDynamicSharedMemorySize, BLK_SMEM);
  cudaFuncSetAttribute(k_out_mma,   cudaFuncAttributeMaxDynamicSharedMemorySize, OUT_SMEM);
  cudaFuncSetAttribute(k_gram,      cudaFuncAttributeMaxDynamicSharedMemorySize, GRAM_SMEM_BYTES);

  k_prep<<<(3*HID*HID + EMB*HID + 255)/256, 256>>>(Wb, W_out);
  k_gemm_in<<<MROWS/64, 256>>>(H, pairs, W_in, b_in);
  for (int k=0;k<3;k++)
    k_block_mma<<<MROWS/64, 256, BLK_SMEM>>>(k, bb + k*HID, lng + k*HID, lnb + k*HID);
  k_out_mma<<<MROWS/128, 256, OUT_SMEM>>>(b_out, lnf_g, lnf_b);
  k_gram<<<dim3(4, NBATCH), 256, GRAM_SMEM_BYTES>>>();
  k_final<<<NBATCH, 256>>>(pairs, out);
}

// round 4
// speedup vs baseline: 2.6847x; 1.4987x over previous
#include <cuda_runtime.h>
#include <cuda_bf16.h>
#include <math.h>
#include <stdint.h>

#define NBATCH 64
#define HALF   512
#define INDIM  64
#define HID    256
#define EMB    128
#define MROWS  (NBATCH*HALF)   // 32768 unique rows
#define LN_EPS 1e-5f

// weight regions inside g_bt_*: [0,196608) Wb^T, [196608,229376) W_out^T,
// [229376,245760) W_in^T (256 n x 64 k)
#define WOUT_OFS (3*HID*HID)
#define WIN_OFS  (3*HID*HID + EMB*HID)
#define WT_TOTAL (WIN_OFS + HID*INDIM)

// ---------------- device scratch (allocation is forbidden) ------------------
__device__ __align__(16) __nv_bfloat16 g_ah[MROWS*HID];   // h hi
__device__ __align__(16) __nv_bfloat16 g_al[MROWS*HID];   // h lo
__device__ __align__(16) __nv_bfloat16 g_bt_hi[WT_TOTAL];
__device__ __align__(16) __nv_bfloat16 g_bt_lo[WT_TOTAL];
__device__ __align__(16) __nv_bfloat16 g_zh[MROWS*EMB];   // z hi
__device__ __align__(16) __nv_bfloat16 g_zl[MROWS*EMB];   // z lo
__device__ float g_sq[MROWS];
__device__ float g_s [MROWS];

// ---------------- helpers ----------------------------------------------------
__device__ __forceinline__ uint32_t smem_u32(const void* p){
  uint32_t a;
  asm("{ .reg .u64 t; cvta.to.shared.u64 t, %1; cvt.u32.u64 %0, t; }" : "=r"(a) : "l"(p));
  return a;
}
__device__ __forceinline__ float warp_sum32(float v){
  #pragma unroll
  for (int o=16;o;o>>=1) v += __shfl_xor_sync(0xffffffffu, v, o);
  return v;
}
__device__ __forceinline__ void cp16(uint32_t dst, const void* src){
  asm volatile("cp.async.cg.shared.global [%0], [%1], 16;\n" :: "r"(dst), "l"(src));
}
#define CP_COMMIT() asm volatile("cp.async.commit_group;\n" ::: "memory")
#define CP_WAIT(n)  asm volatile("cp.async.wait_group %0;\n" :: "n"(n) : "memory")

__device__ __forceinline__ void ldsm4(uint32_t (&r)[4], uint32_t addr){
  asm volatile("ldmatrix.sync.aligned.m8n8.x4.shared.b16 {%0,%1,%2,%3}, [%4];\n"
    : "=r"(r[0]),"=r"(r[1]),"=r"(r[2]),"=r"(r[3]) : "r"(addr));
}
__device__ __forceinline__ void mma16816(float (&d)[4], const uint32_t (&a)[4],
                                         uint32_t b0, uint32_t b1){
  asm volatile("mma.sync.aligned.m16n8k16.row.col.f32.bf16.bf16.f32 "
    "{%0,%1,%2,%3}, {%4,%5,%6,%7}, {%8,%9}, {%0,%1,%2,%3};\n"
    : "+f"(d[0]),"+f"(d[1]),"+f"(d[2]),"+f"(d[3])
    : "r"(a[0]),"r"(a[1]),"r"(a[2]),"r"(a[3]), "r"(b0),"r"(b1));
}
// rows of 64B (32 bf16); chunk c in 0..3; XOR swizzle for conflict-free LDSM
__device__ __forceinline__ uint32_t swz(int r, int c){
  return (uint32_t)(r*64 + ((c ^ ((r>>1)&3))<<4));
}
__device__ __forceinline__ void split_bf16(float x, __nv_bfloat16& h, __nv_bfloat16& l){
  h = __float2bfloat16(x);
  l = __float2bfloat16(x - __bfloat162float(h));
}

// warp tile 32 rows x 64 cols, one k32 chunk, bf16x3 accumulate
__device__ __forceinline__ void warp_mma_chunk(
    float (&acc)[2][8][4],
    uint32_t aH, uint32_t aL, uint32_t bH, uint32_t bL,
    int wm, int wn, int lane)
{
  #pragma unroll
  for (int kk=0; kk<2; kk++){
    uint32_t ah[2][4], al[2][4];
    #pragma unroll
    for (int mi=0; mi<2; mi++){
      int row = wm*32 + mi*16 + (lane & 15);
      int c   = kk*2 + (lane >> 4);
      uint32_t off = swz(row, c);
      ldsm4(ah[mi], aH + off);
      ldsm4(al[mi], aL + off);
    }
    #pragma unroll
    for (int p=0; p<4; p++){
      int n = wn*64 + p*16 + ((lane>>4)<<3) + (lane & 7);
      int c = kk*2 + ((lane>>3)&1);
      uint32_t off = swz(n, c);
      uint32_t bh[4], bl[4];
      ldsm4(bh, bH + off);
      ldsm4(bl, bL + off);
      #pragma unroll
      for (int mi=0; mi<2; mi++){
        #pragma unroll
        for (int h=0; h<2; h++){
          mma16816(acc[mi][p*2+h], ah[mi], bh[2*h], bh[2*h+1]);
          mma16816(acc[mi][p*2+h], ah[mi], bl[2*h], bl[2*h+1]);
          mma16816(acc[mi][p*2+h], al[mi], bh[2*h], bh[2*h+1]);
        }
      }
    }
  }
}

// warp tile 32 rows x 32 cols (for gram), one k32 chunk, bf16x3
__device__ __forceinline__ void warp_mma_chunk32(
    float (&acc)[2][4][4],
    uint32_t aH, uint32_t aL, uint32_t bH, uint32_t bL,
    int wm, int wn, int lane)
{
  #pragma unroll
  for (int kk=0; kk<2; kk++){
    uint32_t ah[2][4], al[2][4];
    #pragma unroll
    for (int mi=0; mi<2; mi++){
      int row = wm*32 + mi*16 + (lane & 15);
      int c   = kk*2 + (lane >> 4);
      uint32_t off = swz(row, c);
      ldsm4(ah[mi], aH + off);
      ldsm4(al[mi], aL + off);
    }
    #pragma unroll
    for (int p=0; p<2; p++){
      int n = wn*32 + p*16 + ((lane>>4)<<3) + (lane & 7);
      int c = kk*2 + ((lane>>3)&1);
      uint32_t off = swz(n, c);
      uint32_t bh[4], bl[4];
      ldsm4(bh, bH + off);
      ldsm4(bl, bL + off);
      #pragma unroll
      for (int mi=0; mi<2; mi++){
        #pragma unroll
        for (int h=0; h<2; h++){
          mma16816(acc[mi][p*2+h], ah[mi], bh[2*h], bh[2*h+1]);
          mma16816(acc[mi][p*2+h], ah[mi], bl[2*h], bl[2*h+1]);
          mma16816(acc[mi][p*2+h], al[mi], bh[2*h], bh[2*h+1]);
        }
      }
    }
  }
}

// ---------------------------------------------------------------------------
// prep: transpose + hi/lo split of Wb, W_out, W_in into [n][k] layout
// ---------------------------------------------------------------------------
__global__ void __launch_bounds__(256) k_prep(
    const float* __restrict__ Wb, const float* __restrict__ Wout,
    const float* __restrict__ Win)
{
  int i = blockIdx.x*256 + threadIdx.x;
  float v;
  if (i < WOUT_OFS){
    int layer = i >> 16;
    int n  = (i >> 8) & 255;
    int kk = i & 255;
    v = Wb[layer*HID*HID + kk*HID + n];
  } else if (i < WIN_OFS){
    int j = i - WOUT_OFS;
    int n  = j >> 8;
    int kk = j & 255;
    v = Wout[kk*EMB + n];
  } else if (i < WT_TOTAL){
    int j = i - WIN_OFS;
    int n  = j >> 6;    // 0..255
    int kk = j & 63;    // 0..63
    v = Win[kk*HID + n];
  } else return;
  __nv_bfloat16 h, l; split_bf16(v, h, l);
  g_bt_hi[i] = h; g_bt_lo[i] = l;
}

// ---------------------------------------------------------------------------
// k_gemm_in_mma: h = |H[li]-H[ri]| @ W_in + b_in  (bf16x3 mma, K=64)
// CTA: 64 rows x 256 cols, 8 warps (2M x 4N).
// SMEM: A_hi[0,8K) A_lo[8K,16K) B_hi[16K,48K) B_lo[48K,80K) prm[80K,81K)
// ---------------------------------------------------------------------------
#define GIN_SMEM (81920 + 1024)
__global__ void __launch_bounds__(256) k_gemm_in_mma(
    const float* __restrict__ H, const int* __restrict__ pairs,
    const float* __restrict__ bias)
{
  extern __shared__ char smem[];
  __shared__ int li_sm[64], ri_sm[64];
  const uint32_t sb = smem_u32(smem);
  const int tid = threadIdx.x, lane = tid&31, wid = tid>>5;
  const int wm = wid>>2, wn = wid&3;
  const int row0 = blockIdx.x * 64;
  const __nv_bfloat16* __restrict__ WtHi = g_bt_hi + WIN_OFS;
  const __nv_bfloat16* __restrict__ WtLo = g_bt_lo + WIN_OFS;

  float* prm = (float*)(smem + 81920);
  prm[tid] = bias[tid];
  if (tid < 64){
    li_sm[tid] = pairs[2*(row0+tid)];
    ri_sm[tid] = pairs[2*(row0+tid)+1];
  }

  // B: W_in^T (256 n x 64 k) hi/lo via cp.async, 2 k-chunks of 32
  #pragma unroll
  for (int u=0; u<8; u++){
    int e = tid + u*256;      // 0..2047
    int n = e>>3, q3 = e&7;
    int c = q3>>2, qq = q3&3;
    uint32_t off = (uint32_t)(c*16384) + swz(n, qq);
    cp16(sb + 16384 + off, WtHi + (size_t)n*INDIM + q3*8);
    cp16(sb + 49152 + off, WtLo + (size_t)n*INDIM + q3*8);
  }
  CP_COMMIT();
  __syncthreads();   // li/ri visible

  // A: compute delta, split, STS
  #pragma unroll
  for (int u=0; u<2; u++){
    int e = tid + u*256;      // 0..511
    int r = e>>3, q3 = e&7;
    int c = q3>>2, qq = q3&3;
    const float4* pl = (const float4*)(H + (size_t)li_sm[r]*INDIM + q3*8);
    const float4* pr = (const float4*)(H + (size_t)ri_sm[r]*INDIM + q3*8);
    float4 a0 = pl[0], a1 = pl[1];
    float4 b0 = pr[0], b1 = pr[1];
    float d[8] = { fabsf(a0.x-b0.x), fabsf(a0.y-b0.y), fabsf(a0.z-b0.z), fabsf(a0.w-b0.w),
                   fabsf(a1.x-b1.x), fabsf(a1.y-b1.y), fabsf(a1.z-b1.z), fabsf(a1.w-b1.w) };
    __nv_bfloat16 oh[8], ol[8];
    #pragma unroll
    for (int i=0;i<8;i++) split_bf16(d[i], oh[i], ol[i]);
    uint32_t off = (uint32_t)(c*4096) + swz(r, qq);
    *(uint4*)(smem + off)        = *(uint4*)oh;
    *(uint4*)(smem + 8192 + off) = *(uint4*)ol;
  }
  CP_WAIT(0);
  __syncthreads();

  float acc[2][8][4];
  #pragma unroll
  for (int mi=0;mi<2;mi++)
    #pragma unroll
    for (int j=0;j<8;j++)
      #pragma unroll
      for (int q=0;q<4;q++) acc[mi][j][q]=0.f;

  #pragma unroll
  for (int c=0;c<2;c++)
    warp_mma_chunk(acc, sb + c*4096, sb + 8192 + c*4096,
                   sb + 16384 + c*16384, sb + 49152 + c*16384, wm, wn, lane);
  __syncthreads();

  // stage accums, then bias + split + coalesced writeback
  float* res = (float*)smem;   // [64][264]
  #pragma unroll
  for (int mi=0;mi<2;mi++){
    int r0r = wm*32 + mi*16 + (lane>>2);
    #pragma unroll
    for (int j=0;j<8;j++){
      int col = wn*64 + j*8 + 2*(lane&3);
      res[r0r*264+col]       = acc[mi][j][0];
      res[r0r*264+col+1]     = acc[mi][j][1];
      res[(r0r+8)*264+col]   = acc[mi][j][2];
      res[(r0r+8)*264+col+1] = acc[mi][j][3];
    }
  }
  __syncthreads();

  for (int u=tid; u<2048; u+=256){
    int r = u>>5, q = u&31;
    float v[8];
    *(float4*)v     = *(float4*)(res + r*264 + q*8);
    *(float4*)(v+4) = *(float4*)(res + r*264 + q*8 + 4);
    __nv_bfloat16 oh[8], ol[8];
    #pragma unroll
    for (int i=0;i<8;i++){
      float x = v[i] + prm[q*8+i];
      split_bf16(x, oh[i], ol[i]);
    }
    size_t gi = (size_t)(row0+r)*HID + q*8;
    *(uint4*)(g_ah + gi) = *(uint4*)oh;
    *(uint4*)(g_al + gi) = *(uint4*)ol;
  }
}

// ---------------------------------------------------------------------------
// k_block_mma: h = h + relu(LN(h @ Wb + bb))  via mma.sync bf16x3
// CTA: 64 rows x 256 cols, 8 warps (2M x 4N), K=256 in 8 chunks of 32.
// ---------------------------------------------------------------------------
#define BLK_STAGE 40960
#define BLK_SMEM  (81920 + 3072)
__global__ void __launch_bounds__(256) k_block_mma(
    int layer, const float* __restrict__ bb,
    const float* __restrict__ lg, const float* __restrict__ lb)
{
  extern __shared__ char smem[];
  const uint32_t sb = smem_u32(smem);
  const int tid = threadIdx.x, lane = tid&31, wid = tid>>5;
  const int wm = wid>>2, wn = wid&3;
  const int row0 = blockIdx.x * 64;
  const __nv_bfloat16* __restrict__ WtHi = g_bt_hi + (size_t)layer*HID*HID;
  const __nv_bfloat16* __restrict__ WtLo = g_bt_lo + (size_t)layer*HID*HID;

  float* prm = (float*)(smem + 81920);
  prm[tid] = bb[tid]; prm[256+tid] = lg[tid]; prm[512+tid] = lb[tid];

  const int ar = tid>>2, aq = tid&3;
  auto load_chunk = [&](int c, int buf){
    uint32_t base = sb + (uint32_t)buf*BLK_STAGE;
    int kc = c*32;
    {
      size_t gi = (size_t)(row0+ar)*HID + kc + aq*8;
      uint32_t off = swz(ar, aq);
      cp16(base + off,        g_ah + gi);
      cp16(base + 4096 + off, g_al + gi);
    }
    #pragma unroll
    for (int u=0; u<4; u++){
      int e = tid + u*256;
      int n = e>>2, q = e&3;
      size_t gi = (size_t)n*HID + kc + q*8;
      uint32_t off = swz(n, q);
      cp16(base + 8192  + off, WtHi + gi);
      cp16(base + 24576 + off, WtLo + gi);
    }
    CP_COMMIT();
  };

  float acc[2][8][4];
  #pragma unroll
  for (int mi=0;mi<2;mi++)
    #pragma unroll
    for (int j=0;j<8;j++)
      #pragma unroll
      for (int q=0;q<4;q++) acc[mi][j][q]=0.f;

  load_chunk(0,0);
  load_chunk(1,1);
  for (int c=0;c<8;c++){
    if (c<6) { CP_WAIT(1); } else { CP_WAIT(0); }
    __syncthreads();
    uint32_t base = sb + (uint32_t)(c&1)*BLK_STAGE;
    warp_mma_chunk(acc, base, base+4096, base+8192, base+24576, wm, wn, lane);
    __syncthreads();
    if (c<6) load_chunk(c+2, c&1);
  }

  float* res = (float*)smem;   // [64][264]
  #pragma unroll
  for (int mi=0;mi<2;mi++){
    int r0r = wm*32 + mi*16 + (lane>>2);
    #pragma unroll
    for (int j=0;j<8;j++){
      int col = wn*64 + j*8 + 2*(lane&3);
      res[r0r*264+col]       = acc[mi][j][0];
      res[r0r*264+col+1]     = acc[mi][j][1];
      res[(r0r+8)*264+col]   = acc[mi][j][2];
      res[(r0r+8)*264+col+1] = acc[mi][j][3];
    }
  }
  __syncthreads();

  #pragma unroll
  for (int r8=0;r8<8;r8++){
    int row = wid*8 + r8;
    float v[8]; float s1=0.f;
    #pragma unroll
    for (int i=0;i<8;i++){ v[i]=res[row*264 + lane + 32*i] + prm[lane+32*i]; s1+=v[i]; }
    s1 = warp_sum32(s1);
    float mu = s1*(1.f/256.f);
    float s2=0.f;
    #pragma unroll
    for (int i=0;i<8;i++){ float d=v[i]-mu; s2+=d*d; }
    s2 = warp_sum32(s2);
    float rs = rsqrtf(s2*(1.f/256.f)+LN_EPS);
    #pragma unroll
    for (int i=0;i<8;i++){
      int cc = lane+32*i;
      float t = (v[i]-mu)*rs*prm[256+cc] + prm[512+cc];
      res[row*264+cc] = fmaxf(t, 0.f);
    }
  }
  __syncthreads();

  for (int u=tid; u<2048; u+=256){
    int r = u>>5, q = u&31;
    float v[8];
    *(float4*)v     = *(float4*)(res + r*264 + q*8);
    *(float4*)(v+4) = *(float4*)(res + r*264 + q*8 + 4);
    size_t gi = (size_t)(row0+r)*HID + q*8;
    uint4 hh = *(const uint4*)(g_ah + gi);
    uint4 ll = *(const uint4*)(g_al + gi);
    const __nv_bfloat16* hp = (const __nv_bfloat16*)&hh;
    const __nv_bfloat16* lp = (const __nv_bfloat16*)&ll;
    __nv_bfloat16 oh[8], ol[8];
    #pragma unroll
    for (int i=0;i<8;i++){
      float x = __bfloat162float(hp[i]) + __bfloat162float(lp[i]) + v[i];
      split_bf16(x, oh[i], ol[i]);
    }
    *(uint4*)(g_ah + gi) = *(uint4*)oh;
    *(uint4*)(g_al + gi) = *(uint4*)ol;
  }
}

// ---------------------------------------------------------------------------
// k_out_mma: z = LN(h @ W_out + b_out) -> g_zh/g_zl bf16 pair, sq = sum z^2,
// and zero g_s for the gram atomics. CTA 128x128, 8 warps (4M x 2N).
// ---------------------------------------------------------------------------
#define OUT_STAGE 32768
#define OUT_SMEM  (69632 + 1536)
__global__ void __launch_bounds__(256) k_out_mma(
    const float* __restrict__ bo, const float* __restrict__ lg,
    const float* __restrict__ lb)
{
  extern __shared__ char smem[];
  const uint32_t sb = smem_u32(smem);
  const int tid = threadIdx.x, lane = tid&31, wid = tid>>5;
  const int wm = wid>>1, wn = wid&1;
  const int row0 = blockIdx.x * 128;
  const __nv_bfloat16* __restrict__ WtHi = g_bt_hi + WOUT_OFS;
  const __nv_bfloat16* __restrict__ WtLo = g_bt_lo + WOUT_OFS;

  float* prm = (float*)(smem + 69632);
  if (tid < 128){ prm[tid]=bo[tid]; prm[128+tid]=lg[tid]; prm[256+tid]=lb[tid]; }

  auto load_chunk = [&](int c, int buf){
    uint32_t base = sb + (uint32_t)buf*OUT_STAGE;
    int kc = c*32;
    #pragma unroll
    for (int u=0; u<2; u++){
      int e = tid + u*256;
      int r = e>>2, q = e&3;
      size_t gi = (size_t)(row0+r)*HID + kc + q*8;
      uint32_t off = swz(r, q);
      cp16(base + off,        g_ah + gi);
      cp16(base + 8192 + off, g_al + gi);
    }
    #pragma unroll
    for (int u=0; u<2; u++){
      int e = tid + u*256;
      int n = e>>2, q = e&3;
      size_t gi = (size_t)n*HID + kc + q*8;
      uint32_t off = swz(n, q);
      cp16(base + 16384 + off, WtHi + gi);
      cp16(base + 24576 + off, WtLo + gi);
    }
    CP_COMMIT();
  };

  float acc[2][8][4];
  #pragma unroll
  for (int mi=0;mi<2;mi++)
    #pragma unroll
    for (int j=0;j<8;j++)
      #pragma unroll
      for (int q=0;q<4;q++) acc[mi][j][q]=0.f;

  load_chunk(0,0);
  load_chunk(1,1);
  for (int c=0;c<8;c++){
    if (c<6) { CP_WAIT(1); } else { CP_WAIT(0); }
    __syncthreads();
    uint32_t base = sb + (uint32_t)(c&1)*OUT_STAGE;
    warp_mma_chunk(acc, base, base+8192, base+16384, base+24576, wm, wn, lane);
    __syncthreads();
    if (c<6) load_chunk(c+2, c&1);
  }

  float* res = (float*)smem;   // [128][136]
  #pragma unroll
  for (int mi=0;mi<2;mi++){
    int r0r = wm*32 + mi*16 + (lane>>2);
    #pragma unroll
    for (int j=0;j<8;j++){
      int col = wn*64 + j*8 + 2*(lane&3);
      res[r0r*136+col]       = acc[mi][j][0];
      res[r0r*136+col+1]     = acc[mi][j][1];
      res[(r0r+8)*136+col]   = acc[mi][j][2];
      res[(r0r+8)*136+col+1] = acc[mi][j][3];
    }
  }
  __syncthreads();

  #pragma unroll
  for (int r16=0;r16<16;r16++){
    int row = wid*16 + r16;
    float v[4]; float s1=0.f;
    #pragma unroll
    for (int i=0;i<4;i++){ v[i]=res[row*136 + lane + 32*i] + prm[lane+32*i]; s1+=v[i]; }
    s1 = warp_sum32(s1);
    float mu = s1*(1.f/128.f);
    float s2=0.f;
    #pragma unroll
    for (int i=0;i<4;i++){ float d=v[i]-mu; s2+=d*d; }
    s2 = warp_sum32(s2);
    float rs = rsqrtf(s2*(1.f/128.f)+LN_EPS);
    float qs=0.f;
    #pragma unroll
    for (int i=0;i<4;i++){
      int cc = lane+32*i;
      float t = (v[i]-mu)*rs*prm[128+cc] + prm[256+cc];
      res[row*136+cc] = t;
      qs += t*t;
    }
    qs = warp_sum32(qs);
    if (lane==0){ g_sq[row0+row] = qs; g_s[row0+row] = 0.f; }
  }
  __syncthreads();

  // bf16-pair writeback of z
  for (int u=tid; u<2048; u+=256){
    int r = u>>4, q = u&15;
    float v[8];
    *(float4*)v     = *(float4*)(res + r*136 + q*8);
    *(float4*)(v+4) = *(float4*)(res + r*136 + q*8 + 4);
    __nv_bfloat16 oh[8], ol[8];
    #pragma unroll
    for (int i=0;i<8;i++) split_bf16(v[i], oh[i], ol[i]);
    size_t gi = (size_t)(row0+r)*EMB + q*8;
    *(uint4*)(g_zh + gi) = *(uint4*)oh;
    *(uint4*)(g_zl + gi) = *(uint4*)ol;
  }
}

// ---------------------------------------------------------------------------
// k_gram_mma: per-batch 512x512 pairwise distances via symmetric 64x64 tiles.
// Grid (36 tile-pairs, 64 batches). CTA 128 threads, 4 warps (2M x 2N),
// warp tile 32x32. bf16x3 dot, dist=sqrt(max(sq_r+sq_c-2dot,1e-12)).
// Row-sums atomicAdd to g_s; off-diag tiles also add column-sums.
// SMEM: A_hi[0,16K) A_lo[16K,32K) B_hi[32K,48K) B_lo[48K,64K), chunks of 4KB.
// ---------------------------------------------------------------------------
#define GRM_SMEM 65536
__global__ void __launch_bounds__(128) k_gram_mma()
{
  extern __shared__ char smem[];
  const uint32_t sb = smem_u32(smem);
  const int tid = threadIdx.x, lane = tid&31, wid = tid>>5;
  const int wm = wid>>1, wn = wid&1;

  int t = blockIdx.x, rt = 0;
  while (t >= 8 - rt){ t -= 8 - rt; rt++; }
  const int ct = rt + t;
  const bool diag = (rt == ct);
  const int bofs = blockIdx.y * HALF;
  const int r0 = bofs + rt*64;
  const int c0 = bofs + ct*64;

  // load A tile (64 rows x 128 K, hi/lo) in 4 k-chunk layout
  #pragma unroll
  for (int u=0; u<8; u++){
    int e = tid + u*128;       // 0..1023
    int r = e>>4, tt = e&15;
    int c = tt>>2, q = tt&3;
    uint32_t off = (uint32_t)(c*4096) + swz(r, q);
    size_t gi = (size_t)(r0+r)*EMB + c*32 + q*8;
    cp16(sb + off,         g_zh + gi);
    cp16(sb + 16384 + off, g_zl + gi);
  }
  if (!diag){
    #pragma unroll
    for (int u=0; u<8; u++){
      int e = tid + u*128;
      int r = e>>4, tt = e&15;
      int c = tt>>2, q = tt&3;
      uint32_t off = (uint32_t)(c*4096) + swz(r, q);
      size_t gi = (size_t)(c0+r)*EMB + c*32 + q*8;
      cp16(sb + 32768 + off, g_zh + gi);
      cp16(sb + 49152 + off, g_zl + gi);
    }
  }
  CP_COMMIT(); CP_WAIT(0);
  __syncthreads();

  const uint32_t bHb = diag ? sb : (sb + 32768);
  const uint32_t bLb = diag ? (sb + 16384) : (sb + 49152);

  float acc[2][4][4];
  #pragma unroll
  for (int mi=0;mi<2;mi++)
    #pragma unroll
    for (int j=0;j<4;j++)
      #pragma unroll
      for (int q=0;q<4;q++) acc[mi][j][q]=0.f;

  #pragma unroll
  for (int c=0;c<4;c++)
    warp_mma_chunk32(acc, sb + c*4096, sb + 16384 + c*4096,
                     bHb + c*4096, bLb + c*4096, wm, wn, lane);

  // epilogue: distances, row-sums (and col-sums for off-diag)
  float sqr[4];
  #pragma unroll
  for (int mi=0;mi<2;mi++)
    #pragma unroll
    for (int h=0;h<2;h++)
      sqr[mi*2+h] = g_sq[r0 + wm*32 + mi*16 + (lane>>2) + h*8];

  float rsum[4] = {0.f,0.f,0.f,0.f};
  float csum[8] = {0.f,0.f,0.f,0.f,0.f,0.f,0.f,0.f};
  #pragma unroll
  for (int j=0;j<4;j++){
    int colg = c0 + wn*32 + j*8 + 2*(lane&3);
    float sqc0 = g_sq[colg], sqc1 = g_sq[colg+1];
    #pragma unroll
    for (int mi=0;mi<2;mi++){
      float d0 = sqrtf(fmaxf(sqr[mi*2+0] + sqc0 - 2.f*acc[mi][j][0], 1e-12f));
      float d1 = sqrtf(fmaxf(sqr[mi*2+0] + sqc1 - 2.f*acc[mi][j][1], 1e-12f));
      float d2 = sqrtf(fmaxf(sqr[mi*2+1] + sqc0 - 2.f*acc[mi][j][2], 1e-12f));
      float d3 = sqrtf(fmaxf(sqr[mi*2+1] + sqc1 - 2.f*acc[mi][j][3], 1e-12f));
      rsum[mi*2+0] += d0 + d1;
      rsum[mi*2+1] += d2 + d3;
      csum[j*2+0]  += d0 + d2;
      csum[j*2+1]  += d1 + d3;
    }
  }

  // row sums: reduce over quad (lanes differing in bits 0,1 share a row)
  #pragma unroll
  for (int i=0;i<4;i++){
    rsum[i] += __shfl_xor_sync(0xffffffffu, rsum[i], 1);
    rsum[i] += __shfl_xor_sync(0xffffffffu, rsum[i], 2);
  }
  if ((lane & 3) == 0){
    #pragma unroll
    for (int mi=0;mi<2;mi++)
      #pragma unroll
      for (int h=0;h<2;h++)
        atomicAdd(&g_s[r0 + wm*32 + mi*16 + (lane>>2) + h*8], rsum[mi*2+h]);
  }

  if (!diag){
    // col sums: reduce over lanes differing in bits 2,3,4 (rows)
    #pragma unroll
    for (int i=0;i<8;i++){
      csum[i] += __shfl_xor_sync(0xffffffffu, csum[i], 4);
      csum[i] += __shfl_xor_sync(0xffffffffu, csum[i], 8);
      csum[i] += __shfl_xor_sync(0xffffffffu, csum[i], 16);
    }
    if ((lane >> 2) == 0){
      #pragma unroll
      for (int j=0;j<4;j++){
        int colg = c0 + wn*32 + j*8 + 2*(lane&3);
        atomicAdd(&g_s[colg],   csum[j*2+0]);
        atomicAdd(&g_s[colg+1], csum[j*2+1]);
      }
    }
  }
}

// ---------------------------------------------------------------------------
// k_final: softmax over 512 unique scores + weighted sum; write w and f.
// ---------------------------------------------------------------------------
__global__ void __launch_bounds__(256) k_final(
    const int* __restrict__ pairs, float* __restrict__ out)
{
  __shared__ float ev[512];
  __shared__ float red[256];
  const int b = blockIdx.x, tid = threadIdx.x;
  const float scale = 1.f/(512.f*0.25f);
  float x0 = g_s[b*HALF + tid      ]*scale;
  float x1 = g_s[b*HALF + 256 + tid]*scale;

  red[tid] = fmaxf(x0,x1);
  __syncthreads();
  for (int o=128;o;o>>=1){ if(tid<o) red[tid]=fmaxf(red[tid],red[tid+o]); __syncthreads(); }
  float mx = red[0];
  __syncthreads();

  float e0 = expf(x0-mx), e1 = expf(x1-mx);
  ev[tid] = e0; ev[tid+256] = e1;
  red[tid] = e0+e1;
  __syncthreads();
  for (int o=128;o;o>>=1){ if(tid<o) red[tid]+=red[tid+o]; __syncthreads(); }
  float inv = 1.f/red[0];

  float* wout = out + NBATCH*EMB;
  {
    int p = b*HALF + tid;
    float wv = ev[tid]*inv*0.5f;
    wout[pairs[2*p]]   = wv;
    wout[pairs[2*p+1]] = wv;
    p = b*HALF + 256 + tid;
    wv = ev[tid+256]*inv*0.5f;
    wout[pairs[2*p]]   = wv;
    wout[pairs[2*p+1]] = wv;
  }

  const int col = tid & 127, part = tid >> 7;
  float fs = 0.f;
  for (int i = part*256; i < part*256+256; i++){
    size_t gi = (size_t)(b*HALF+i)*EMB + col;
    float zv = __bfloat162float(g_zh[gi]) + __bfloat162float(g_zl[gi]);
    fs += ev[i]*inv * zv;
  }
  __syncthreads();
  red[tid] = fs;
  __syncthreads();
  if (tid < 128) out[b*EMB + tid] = red[tid] + red[tid+128];
}

// ---------------------------------------------------------------------------
extern "C" void kernel_launch(void* const* d_in, const int* in_sizes, int n_in,
                              void* d_out, int out_size)
{
  const float* H     = (const float*)d_in[0];
  const int*   pairs = (const int*)  d_in[2];
  const float* W_in  = (const float*)d_in[3];
  const float* b_in  = (const float*)d_in[4];
  const float* Wb    = (const float*)d_in[5];
  const float* bb    = (const float*)d_in[6];
  const float* lng   = (const float*)d_in[7];
  const float* lnb   = (const float*)d_in[8];
  const float* W_out = (const float*)d_in[9];
  const float* b_out = (const float*)d_in[10];
  const float* lnf_g = (const float*)d_in[11];
  const float* lnf_b = (const float*)d_in[12];
  float* out = (float*)d_out;

  cudaFuncSetAttribute(k_gemm_in_mma, cudaFuncAttributeMaxDynamicSharedMemorySize, GIN_SMEM);
  cudaFuncSetAttribute(k_block_mma,   cudaFuncAttributeMaxDynamicSharedMemorySize, BLK_SMEM);
  cudaFuncSetAttribute(k_out_mma,     cudaFuncAttributeMaxDynamicSharedMemorySize, OUT_SMEM);
  cudaFuncSetAttribute(k_gram_mma,    cudaFuncAttributeMaxDynamicSharedMemorySize, GRM_SMEM);

  k_prep<<<(WT_TOTAL + 255)/256, 256>>>(Wb, W_out, W_in);
  k_gemm_in_mma<<<MROWS/64, 256, GIN_SMEM>>>(H, pairs, b_in);
  for (int k=0;k<3;k++)
    k_block_mma<<<MROWS/64, 256, BLK_SMEM>>>(k, bb + k*HID, lng + k*HID, lnb + k*HID);
  k_out_mma<<<MROWS/128, 256, OUT_SMEM>>>(b_out, lnf_g, lnf_b);
  k_gram_mma<<<dim3(36, NBATCH), 128, GRM_SMEM>>>();
  k_final<<<NBATCH, 256>>>(pairs, out);
}

// round 5
// speedup vs baseline: 3.0171x; 1.1238x over previous
#include <cuda_runtime.h>
#include <cuda_bf16.h>
#include <math.h>
#include <stdint.h>

#define NBATCH 64
#define HALF   512
#define INDIM  64
#define HID    256
#define EMB    128
#define MROWS  (NBATCH*HALF)   // 32768 unique rows
#define LN_EPS 1e-5f

// weight regions inside g_bt_*
#define WOUT_OFS (3*HID*HID)
#define WIN_OFS  (3*HID*HID + EMB*HID)
#define WT_TOTAL (WIN_OFS + HID*INDIM)

// ---------------- device scratch (allocation is forbidden) ------------------
__device__ __align__(16) __nv_bfloat16 g_bt_hi[WT_TOTAL];
__device__ __align__(16) __nv_bfloat16 g_bt_lo[WT_TOTAL];
__device__ __align__(16) __nv_bfloat16 g_zh[MROWS*EMB];   // z hi
__device__ __align__(16) __nv_bfloat16 g_zl[MROWS*EMB];   // z lo
__device__ float g_sq[MROWS];
__device__ float g_s [MROWS];

// ---------------- helpers ----------------------------------------------------
__device__ __forceinline__ uint32_t smem_u32(const void* p){
  uint32_t a;
  asm("{ .reg .u64 t; cvta.to.shared.u64 t, %1; cvt.u32.u64 %0, t; }" : "=r"(a) : "l"(p));
  return a;
}
__device__ __forceinline__ void cp16(uint32_t dst, const void* src){
  asm volatile("cp.async.cg.shared.global [%0], [%1], 16;\n" :: "r"(dst), "l"(src));
}
#define CP_COMMIT() asm volatile("cp.async.commit_group;\n" ::: "memory")
#define CP_WAIT(n)  asm volatile("cp.async.wait_group %0;\n" :: "n"(n) : "memory")

__device__ __forceinline__ void ldsm4(uint32_t (&r)[4], uint32_t addr){
  asm volatile("ldmatrix.sync.aligned.m8n8.x4.shared.b16 {%0,%1,%2,%3}, [%4];\n"
    : "=r"(r[0]),"=r"(r[1]),"=r"(r[2]),"=r"(r[3]) : "r"(addr));
}
__device__ __forceinline__ void mma16816(float (&d)[4], const uint32_t (&a)[4],
                                         uint32_t b0, uint32_t b1){
  asm volatile("mma.sync.aligned.m16n8k16.row.col.f32.bf16.bf16.f32 "
    "{%0,%1,%2,%3}, {%4,%5,%6,%7}, {%8,%9}, {%0,%1,%2,%3};\n"
    : "+f"(d[0]),"+f"(d[1]),"+f"(d[2]),"+f"(d[3])
    : "r"(a[0]),"r"(a[1]),"r"(a[2]),"r"(a[3]), "r"(b0),"r"(b1));
}
// rows of 64B (32 bf16); 16B column-chunk c in 0..3; XOR swizzle
__device__ __forceinline__ uint32_t swz(int r, int c){
  return (uint32_t)(r*64 + ((c ^ ((r>>1)&3))<<4));
}
__device__ __forceinline__ void split_bf16(float x, __nv_bfloat16& h, __nv_bfloat16& l){
  h = __float2bfloat16(x);
  l = __float2bfloat16(x - __bfloat162float(h));
}
// pack split of two floats into (hi-plane u32, lo-plane u32); v0 -> low 16 bits
__device__ __forceinline__ void split2(float v0, float v1, uint32_t& whi, uint32_t& wlo){
  __nv_bfloat16 h0,l0,h1,l1;
  split_bf16(v0,h0,l0); split_bf16(v1,h1,l1);
  whi = ((uint32_t)__bfloat16_as_ushort(h1)<<16) | (uint32_t)__bfloat16_as_ushort(h0);
  wlo = ((uint32_t)__bfloat16_as_ushort(l1)<<16) | (uint32_t)__bfloat16_as_ushort(l0);
}
__device__ __forceinline__ float bf_lo(uint32_t w){
  return __bfloat162float(__ushort_as_bfloat16((unsigned short)(w & 0xffffu)));
}
__device__ __forceinline__ float bf_hi(uint32_t w){
  return __bfloat162float(__ushort_as_bfloat16((unsigned short)(w >> 16)));
}

// warp tile 32 rows x 64 cols, one k32 chunk, bf16x3 accumulate
__device__ __forceinline__ void warp_mma_chunk(
    float (&acc)[2][8][4],
    uint32_t aH, uint32_t aL, uint32_t bH, uint32_t bL,
    int wm, int wn, int lane)
{
  #pragma unroll
  for (int kk=0; kk<2; kk++){
    uint32_t ah[2][4], al[2][4];
    #pragma unroll
    for (int mi=0; mi<2; mi++){
      int row = wm*32 + mi*16 + (lane & 15);
      int c   = kk*2 + (lane >> 4);
      uint32_t off = swz(row, c);
      ldsm4(ah[mi], aH + off);
      ldsm4(al[mi], aL + off);
    }
    #pragma unroll
    for (int p=0; p<4; p++){
      int n = wn*64 + p*16 + ((lane>>4)<<3) + (lane & 7);
      int c = kk*2 + ((lane>>3)&1);
      uint32_t off = swz(n, c);
      uint32_t bh[4], bl[4];
      ldsm4(bh, bH + off);
      ldsm4(bl, bL + off);
      #pragma unroll
      for (int mi=0; mi<2; mi++){
        #pragma unroll
        for (int h=0; h<2; h++){
          mma16816(acc[mi][p*2+h], ah[mi], bh[2*h], bh[2*h+1]);
          mma16816(acc[mi][p*2+h], ah[mi], bl[2*h], bl[2*h+1]);
          mma16816(acc[mi][p*2+h], al[mi], bh[2*h], bh[2*h+1]);
        }
      }
    }
  }
}

// warp tile 32 rows x 32 cols, one k32 chunk, bf16x3
__device__ __forceinline__ void warp_mma_chunk32(
    float (&acc)[2][4][4],
    uint32_t aH, uint32_t aL, uint32_t bH, uint32_t bL,
    int wm, int wn, int lane)
{
  #pragma unroll
  for (int kk=0; kk<2; kk++){
    uint32_t ah[2][4], al[2][4];
    #pragma unroll
    for (int mi=0; mi<2; mi++){
      int row = wm*32 + mi*16 + (lane & 15);
      int c   = kk*2 + (lane >> 4);
      uint32_t off = swz(row, c);
      ldsm4(ah[mi], aH + off);
      ldsm4(al[mi], aL + off);
    }
    #pragma unroll
    for (int p=0; p<2; p++){
      int n = wn*32 + p*16 + ((lane>>4)<<3) + (lane & 7);
      int c = kk*2 + ((lane>>3)&1);
      uint32_t off = swz(n, c);
      uint32_t bh[4], bl[4];
      ldsm4(bh, bH + off);
      ldsm4(bl, bL + off);
      #pragma unroll
      for (int mi=0; mi<2; mi++){
        #pragma unroll
        for (int h=0; h<2; h++){
          mma16816(acc[mi][p*2+h], ah[mi], bh[2*h], bh[2*h+1]);
          mma16816(acc[mi][p*2+h], ah[mi], bl[2*h], bl[2*h+1]);
          mma16816(acc[mi][p*2+h], al[mi], bh[2*h], bh[2*h+1]);
        }
      }
    }
  }
}

// ---------------------------------------------------------------------------
// prep: transpose + hi/lo split of Wb, W_out, W_in; zero g_s
// ---------------------------------------------------------------------------
__global__ void __launch_bounds__(256) k_prep(
    const float* __restrict__ Wb, const float* __restrict__ Wout,
    const float* __restrict__ Win)
{
  int i = blockIdx.x*256 + threadIdx.x;
  if (i < MROWS) g_s[i] = 0.f;
  float v;
  if (i < WOUT_OFS){
    int layer = i >> 16;
    int n  = (i >> 8) & 255;
    int kk = i & 255;
    v = Wb[layer*HID*HID + kk*HID + n];
  } else if (i < WIN_OFS){
    int j = i - WOUT_OFS;
    int n  = j >> 8;
    int kk = j & 255;
    v = Wout[kk*EMB + n];
  } else if (i < WT_TOTAL){
    int j = i - WIN_OFS;
    int n  = j >> 6;
    int kk = j & 63;
    v = Win[kk*HID + n];
  } else return;
  __nv_bfloat16 h, l; split_bf16(v, h, l);
  g_bt_hi[i] = h; g_bt_lo[i] = l;
}

// ---------------------------------------------------------------------------
// k_mega: fused  delta -> GEMM_in -> 3x(residual LN block) -> GEMM_out+LN
// CTA: 128 rows, 512 threads (16 warps, 4M x 4N). h resident in SMEM as
// swizzled bf16 hi/lo k32-chunk planes. Weights streamed 2-stage via cp.async.
// SMEM map:
//   HHI   [8 planes][128 rows][64B]  64KB
//   HLO                              64KB
//   BST   2 stages x (Bhi 16KB + Blo 16KB) = 64KB
//   PRM   bias/lg/lb  3KB
//   PART  [128][4][2] f  4KB
//   IDX   li/ri  1KB
// ---------------------------------------------------------------------------
#define HHI  0
#define HLO  65536
#define BST  131072
#define PRM  196608
#define PART 199680
#define IDX  203776
#define MEGA_SMEM 204800

__global__ void __launch_bounds__(512) k_mega(
    const float* __restrict__ H, const int* __restrict__ pairs,
    const float* __restrict__ b_in,
    const float* __restrict__ bb, const float* __restrict__ lng,
    const float* __restrict__ lnb,
    const float* __restrict__ bo, const float* __restrict__ lnf_g,
    const float* __restrict__ lnf_b)
{
  extern __shared__ char smem[];
  const uint32_t sb = smem_u32(smem);
  const int tid = threadIdx.x, lane = tid&31, wid = tid>>5;
  const int wm = wid>>2, wn = wid&3;
  const int row0 = blockIdx.x * 128;
  int*   li   = (int*)(smem + IDX);
  int*   ri   = li + 128;
  float* prm  = (float*)(smem + PRM);
  float* part = (float*)(smem + PART);

  if (tid < 128){
    li[tid] = pairs[2*(row0+tid)];
    ri[tid] = pairs[2*(row0+tid)+1];
  }
  if (tid < 256) prm[tid] = b_in[tid];
  __syncthreads();

  // ---- delta = |H[li]-H[ri]| into h planes 0,1 (K=64) ----
  #pragma unroll
  for (int u=0; u<2; u++){
    int e = tid + u*512;          // 0..1023: r 0..127, g 0..7 (8-col groups)
    int r = e>>3, g = e&7;
    const float* pl = H + (size_t)li[r]*INDIM + g*8;
    const float* pr = H + (size_t)ri[r]*INDIM + g*8;
    float4 a0 = *(const float4*)pl,     a1 = *(const float4*)(pl+4);
    float4 b0 = *(const float4*)pr,     b1 = *(const float4*)(pr+4);
    float d0=fabsf(a0.x-b0.x), d1=fabsf(a0.y-b0.y), d2=fabsf(a0.z-b0.z), d3=fabsf(a0.w-b0.w);
    float d4=fabsf(a1.x-b1.x), d5=fabsf(a1.y-b1.y), d6=fabsf(a1.z-b1.z), d7=fabsf(a1.w-b1.w);
    uint32_t h0,h1,h2,h3,l0,l1,l2,l3;
    split2(d0,d1,h0,l0); split2(d2,d3,h1,l1);
    split2(d4,d5,h2,l2); split2(d6,d7,h3,l3);
    uint32_t off = (uint32_t)((g>>2)*8192) + swz(r, g&3);
    *(uint4*)(smem + HHI + off) = make_uint4(h0,h1,h2,h3);
    *(uint4*)(smem + HLO + off) = make_uint4(l0,l1,l2,l3);
  }

  // B-chunk loader: nrows in {256,128}, kstride = K of the weight matrix
  auto loadB = [&](const __nv_bfloat16* BH, const __nv_bfloat16* BL,
                   int nrows, int kstride, int c, int s){
    uint32_t base = sb + BST + (uint32_t)s*32768;
    int iters = (nrows*4)/512;
    for (int u=0; u<iters; u++){
      int e = tid + u*512;
      int n = e>>2, q = e&3;
      size_t gi = (size_t)n*kstride + c*32 + q*8;
      uint32_t off = swz(n, q);
      cp16(base + off,         BH + gi);
      cp16(base + 16384 + off, BL + gi);
    }
    CP_COMMIT();
  };

  // ================= layer 0: h = delta @ W_in + b_in =================
  {
    const __nv_bfloat16* BH = g_bt_hi + WIN_OFS;
    const __nv_bfloat16* BL = g_bt_lo + WIN_OFS;
    loadB(BH, BL, 256, INDIM, 0, 0);
    loadB(BH, BL, 256, INDIM, 1, 1);
    float acc[2][8][4];
    #pragma unroll
    for (int mi=0;mi<2;mi++)
      #pragma unroll
      for (int j=0;j<8;j++)
        #pragma unroll
        for (int q=0;q<4;q++) acc[mi][j][q]=0.f;
    CP_WAIT(0);
    __syncthreads();
    warp_mma_chunk(acc, sb+HHI,      sb+HLO,      sb+BST,       sb+BST+16384,       wm, wn, lane);
    warp_mma_chunk(acc, sb+HHI+8192, sb+HLO+8192, sb+BST+32768, sb+BST+32768+16384, wm, wn, lane);
    __syncthreads();   // delta reads complete before overwriting planes

    // epilogue: h = acc + b_in -> write all 8 planes
    #pragma unroll
    for (int j=0;j<8;j++){
      int col = wn*64 + j*8 + 2*(lane&3);
      float b0 = prm[col], b1 = prm[col+1];
      int p = wn*2 + (j>>2), qj = j&3;
      #pragma unroll
      for (int mi=0;mi<2;mi++){
        #pragma unroll
        for (int h=0;h<2;h++){
          int rl = wm*32 + mi*16 + (lane>>2) + h*8;
          uint32_t adr = (uint32_t)p*8192 + swz(rl, qj) + 4*(lane&3);
          uint32_t whi, wlo;
          split2(acc[mi][j][h*2]+b0, acc[mi][j][h*2+1]+b1, whi, wlo);
          *(uint32_t*)(smem + HHI + adr) = whi;
          *(uint32_t*)(smem + HLO + adr) = wlo;
        }
      }
    }
    __syncthreads();
  }

  // ================= layers 1..3: h += relu(LN(h @ Wb + bb)) =================
  for (int L=0; L<3; L++){
    const __nv_bfloat16* BH = g_bt_hi + (size_t)L*HID*HID;
    const __nv_bfloat16* BL = g_bt_lo + (size_t)L*HID*HID;
    if (tid < 256){
      prm[tid]     = bb [L*HID+tid];
      prm[256+tid] = lng[L*HID+tid];
      prm[512+tid] = lnb[L*HID+tid];
    }
    loadB(BH, BL, 256, HID, 0, 0);
    loadB(BH, BL, 256, HID, 1, 1);

    float acc[2][8][4];
    #pragma unroll
    for (int mi=0;mi<2;mi++)
      #pragma unroll
      for (int j=0;j<8;j++)
        #pragma unroll
        for (int q=0;q<4;q++) acc[mi][j][q]=0.f;

    for (int c=0;c<8;c++){
      if (c<6) { CP_WAIT(1); } else { CP_WAIT(0); }
      __syncthreads();
      uint32_t bbase = sb + BST + (uint32_t)(c&1)*32768;
      warp_mma_chunk(acc, sb+HHI+(uint32_t)c*8192, sb+HLO+(uint32_t)c*8192,
                     bbase, bbase+16384, wm, wn, lane);
      __syncthreads();
      if (c<6) loadB(BH, BL, 256, HID, c+2, c&1);
    }

    // ---- register-resident LN epilogue ----
    float sum[4]={0.f,0.f,0.f,0.f}, ssq[4]={0.f,0.f,0.f,0.f};
    #pragma unroll
    for (int j=0;j<8;j++){
      int col = wn*64 + j*8 + 2*(lane&3);
      float b0 = prm[col], b1 = prm[col+1];
      #pragma unroll
      for (int mi=0;mi<2;mi++){
        acc[mi][j][0]+=b0; acc[mi][j][1]+=b1; acc[mi][j][2]+=b0; acc[mi][j][3]+=b1;
        sum[mi*2+0] += acc[mi][j][0]+acc[mi][j][1];
        ssq[mi*2+0] += acc[mi][j][0]*acc[mi][j][0]+acc[mi][j][1]*acc[mi][j][1];
        sum[mi*2+1] += acc[mi][j][2]+acc[mi][j][3];
        ssq[mi*2+1] += acc[mi][j][2]*acc[mi][j][2]+acc[mi][j][3]*acc[mi][j][3];
      }
    }
    #pragma unroll
    for (int s=0;s<4;s++){
      sum[s]+=__shfl_xor_sync(0xffffffffu,sum[s],1);
      sum[s]+=__shfl_xor_sync(0xffffffffu,sum[s],2);
      ssq[s]+=__shfl_xor_sync(0xffffffffu,ssq[s],1);
      ssq[s]+=__shfl_xor_sync(0xffffffffu,ssq[s],2);
    }
    if ((lane&3)==0){
      #pragma unroll
      for (int mi=0;mi<2;mi++)
        #pragma unroll
        for (int h=0;h<2;h++){
          int row = wm*32 + mi*16 + (lane>>2) + h*8;
          part[(row*4+wn)*2]   = sum[mi*2+h];
          part[(row*4+wn)*2+1] = ssq[mi*2+h];
        }
    }
    __syncthreads();
    float mu[4], rs[4];
    #pragma unroll
    for (int mi=0;mi<2;mi++)
      #pragma unroll
      for (int h=0;h<2;h++){
        int row = wm*32 + mi*16 + (lane>>2) + h*8;
        float s1 = part[(row*4+0)*2]+part[(row*4+1)*2]+part[(row*4+2)*2]+part[(row*4+3)*2];
        float s2 = part[(row*4+0)*2+1]+part[(row*4+1)*2+1]+part[(row*4+2)*2+1]+part[(row*4+3)*2+1];
        int s = mi*2+h;
        mu[s] = s1*(1.f/256.f);
        float var = s2*(1.f/256.f) - mu[s]*mu[s];
        rs[s] = rsqrtf(fmaxf(var,0.f) + LN_EPS);
      }
    #pragma unroll
    for (int j=0;j<8;j++){
      int col = wn*64 + j*8 + 2*(lane&3);
      float lg0 = prm[256+col], lg1 = prm[256+col+1];
      float lb0 = prm[512+col], lb1 = prm[512+col+1];
      int p = wn*2 + (j>>2), qj = j&3;
      #pragma unroll
      for (int mi=0;mi<2;mi++){
        #pragma unroll
        for (int h=0;h<2;h++){
          int rl = wm*32 + mi*16 + (lane>>2) + h*8;
          int s = mi*2+h;
          uint32_t adr = (uint32_t)p*8192 + swz(rl, qj) + 4*(lane&3);
          uint32_t ohh = *(uint32_t*)(smem + HHI + adr);
          uint32_t oll = *(uint32_t*)(smem + HLO + adr);
          float old0 = bf_lo(ohh) + bf_lo(oll);
          float old1 = bf_hi(ohh) + bf_hi(oll);
          float t0 = fmaxf((acc[mi][j][h*2]  -mu[s])*rs[s]*lg0 + lb0, 0.f);
          float t1 = fmaxf((acc[mi][j][h*2+1]-mu[s])*rs[s]*lg1 + lb1, 0.f);
          uint32_t whi, wlo;
          split2(old0+t0, old1+t1, whi, wlo);
          *(uint32_t*)(smem + HHI + adr) = whi;
          *(uint32_t*)(smem + HLO + adr) = wlo;
        }
      }
    }
    __syncthreads();
  }

  // ================= out layer: z = LN(h @ W_out + b_out), sq =================
  {
    const __nv_bfloat16* BH = g_bt_hi + WOUT_OFS;
    const __nv_bfloat16* BL = g_bt_lo + WOUT_OFS;
    if (tid < 128){
      prm[tid]     = bo[tid];
      prm[256+tid] = lnf_g[tid];
      prm[512+tid] = lnf_b[tid];
    }
    loadB(BH, BL, 128, HID, 0, 0);
    loadB(BH, BL, 128, HID, 1, 1);

    float acc[2][4][4];
    #pragma unroll
    for (int mi=0;mi<2;mi++)
      #pragma unroll
      for (int j=0;j<4;j++)
        #pragma unroll
        for (int q=0;q<4;q++) acc[mi][j][q]=0.f;

    for (int c=0;c<8;c++){
      if (c<6) { CP_WAIT(1); } else { CP_WAIT(0); }
      __syncthreads();
      uint32_t bbase = sb + BST + (uint32_t)(c&1)*32768;
      warp_mma_chunk32(acc, sb+HHI+(uint32_t)c*8192, sb+HLO+(uint32_t)c*8192,
                       bbase, bbase+16384, wm, wn, lane);
      __syncthreads();
      if (c<6) loadB(BH, BL, 128, HID, c+2, c&1);
    }

    float sum[4]={0.f,0.f,0.f,0.f}, ssq[4]={0.f,0.f,0.f,0.f};
    #pragma unroll
    for (int j=0;j<4;j++){
      int col = wn*32 + j*8 + 2*(lane&3);
      float b0 = prm[col], b1 = prm[col+1];
      #pragma unroll
      for (int mi=0;mi<2;mi++){
        acc[mi][j][0]+=b0; acc[mi][j][1]+=b1; acc[mi][j][2]+=b0; acc[mi][j][3]+=b1;
        sum[mi*2+0] += acc[mi][j][0]+acc[mi][j][1];
        ssq[mi*2+0] += acc[mi][j][0]*acc[mi][j][0]+acc[mi][j][1]*acc[mi][j][1];
        sum[mi*2+1] += acc[mi][j][2]+acc[mi][j][3];
        ssq[mi*2+1] += acc[mi][j][2]*acc[mi][j][2]+acc[mi][j][3]*acc[mi][j][3];
      }
    }
    #pragma unroll
    for (int s=0;s<4;s++){
      sum[s]+=__shfl_xor_sync(0xffffffffu,sum[s],1);
      sum[s]+=__shfl_xor_sync(0xffffffffu,sum[s],2);
      ssq[s]+=__shfl_xor_sync(0xffffffffu,ssq[s],1);
      ssq[s]+=__shfl_xor_sync(0xffffffffu,ssq[s],2);
    }
    if ((lane&3)==0){
      #pragma unroll
      for (int mi=0;mi<2;mi++)
        #pragma unroll
        for (int h=0;h<2;h++){
          int row = wm*32 + mi*16 + (lane>>2) + h*8;
          part[(row*4+wn)*2]   = sum[mi*2+h];
          part[(row*4+wn)*2+1] = ssq[mi*2+h];
        }
    }
    __syncthreads();
    float mu[4], rs[4];
    #pragma unroll
    for (int mi=0;mi<2;mi++)
      #pragma unroll
      for (int h=0;h<2;h++){
        int row = wm*32 + mi*16 + (lane>>2) + h*8;
        float s1 = part[(row*4+0)*2]+part[(row*4+1)*2]+part[(row*4+2)*2]+part[(row*4+3)*2];
        float s2 = part[(row*4+0)*2+1]+part[(row*4+1)*2+1]+part[(row*4+2)*2+1]+part[(row*4+3)*2+1];
        int s = mi*2+h;
        mu[s] = s1*(1.f/128.f);
        float var = s2*(1.f/128.f) - mu[s]*mu[s];
        rs[s] = rsqrtf(fmaxf(var,0.f) + LN_EPS);
      }
    float qs[4]={0.f,0.f,0.f,0.f};
    #pragma unroll
    for (int j=0;j<4;j++){
      int col = wn*32 + j*8 + 2*(lane&3);
      float lg0 = prm[256+col], lg1 = prm[256+col+1];
      float lb0 = prm[512+col], lb1 = prm[512+col+1];
      #pragma unroll
      for (int mi=0;mi<2;mi++){
        #pragma unroll
        for (int h=0;h<2;h++){
          int rl = wm*32 + mi*16 + (lane>>2) + h*8;
          int s = mi*2+h;
          float t0 = (acc[mi][j][h*2]  -mu[s])*rs[s]*lg0 + lb0;
          float t1 = (acc[mi][j][h*2+1]-mu[s])*rs[s]*lg1 + lb1;
          qs[s] += t0*t0 + t1*t1;
          uint32_t whi, wlo;
          split2(t0, t1, whi, wlo);
          size_t gi = (size_t)(row0+rl)*EMB + col;
          *(uint32_t*)(g_zh + gi) = whi;
          *(uint32_t*)(g_zl + gi) = wlo;
        }
      }
    }
    __syncthreads();   // part free for reuse
    #pragma unroll
    for (int s=0;s<4;s++){
      qs[s]+=__shfl_xor_sync(0xffffffffu,qs[s],1);
      qs[s]+=__shfl_xor_sync(0xffffffffu,qs[s],2);
    }
    if ((lane&3)==0){
      #pragma unroll
      for (int mi=0;mi<2;mi++)
        #pragma unroll
        for (int h=0;h<2;h++){
          int row = wm*32 + mi*16 + (lane>>2) + h*8;
          part[row*4+wn] = qs[mi*2+h];
        }
    }
    __syncthreads();
    if (wn==0 && (lane&3)==0){
      #pragma unroll
      for (int mi=0;mi<2;mi++)
        #pragma unroll
        for (int h=0;h<2;h++){
          int row = wm*32 + mi*16 + (lane>>2) + h*8;
          g_sq[row0+row] = part[row*4+0]+part[row*4+1]+part[row*4+2]+part[row*4+3];
        }
    }
  }
}

// ---------------------------------------------------------------------------
// k_gram_mma: per-batch 512x512 pairwise distances via symmetric 64x64 tiles.
// ---------------------------------------------------------------------------
#define GRM_SMEM 65536
__global__ void __launch_bounds__(128) k_gram_mma()
{
  extern __shared__ char smem[];
  const uint32_t sb = smem_u32(smem);
  const int tid = threadIdx.x, lane = tid&31, wid = tid>>5;
  const int wm = wid>>1, wn = wid&1;

  int t = blockIdx.x, rt = 0;
  while (t >= 8 - rt){ t -= 8 - rt; rt++; }
  const int ct = rt + t;
  const bool diag = (rt == ct);
  const int bofs = blockIdx.y * HALF;
  const int r0 = bofs + rt*64;
  const int c0 = bofs + ct*64;

  #pragma unroll
  for (int u=0; u<8; u++){
    int e = tid + u*128;
    int r = e>>4, tt = e&15;
    int c = tt>>2, q = tt&3;
    uint32_t off = (uint32_t)(c*4096) + swz(r, q);
    size_t gi = (size_t)(r0+r)*EMB + c*32 + q*8;
    cp16(sb + off,         g_zh + gi);
    cp16(sb + 16384 + off, g_zl + gi);
  }
  if (!diag){
    #pragma unroll
    for (int u=0; u<8; u++){
      int e = tid + u*128;
      int r = e>>4, tt = e&15;
      int c = tt>>2, q = tt&3;
      uint32_t off = (uint32_t)(c*4096) + swz(r, q);
      size_t gi = (size_t)(c0+r)*EMB + c*32 + q*8;
      cp16(sb + 32768 + off, g_zh + gi);
      cp16(sb + 49152 + off, g_zl + gi);
    }
  }
  CP_COMMIT(); CP_WAIT(0);
  __syncthreads();

  const uint32_t bHb = diag ? sb : (sb + 32768);
  const uint32_t bLb = diag ? (sb + 16384) : (sb + 49152);

  float acc[2][4][4];
  #pragma unroll
  for (int mi=0;mi<2;mi++)
    #pragma unroll
    for (int j=0;j<4;j++)
      #pragma unroll
      for (int q=0;q<4;q++) acc[mi][j][q]=0.f;

  #pragma unroll
  for (int c=0;c<4;c++)
    warp_mma_chunk32(acc, sb + c*4096, sb + 16384 + c*4096,
                     bHb + c*4096, bLb + c*4096, wm, wn, lane);

  float sqr[4];
  #pragma unroll
  for (int mi=0;mi<2;mi++)
    #pragma unroll
    for (int h=0;h<2;h++)
      sqr[mi*2+h] = g_sq[r0 + wm*32 + mi*16 + (lane>>2) + h*8];

  float rsum[4] = {0.f,0.f,0.f,0.f};
  float csum[8] = {0.f,0.f,0.f,0.f,0.f,0.f,0.f,0.f};
  #pragma unroll
  for (int j=0;j<4;j++){
    int colg = c0 + wn*32 + j*8 + 2*(lane&3);
    float sqc0 = g_sq[colg], sqc1 = g_sq[colg+1];
    #pragma unroll
    for (int mi=0;mi<2;mi++){
      float d0 = sqrtf(fmaxf(sqr[mi*2+0] + sqc0 - 2.f*acc[mi][j][0], 1e-12f));
      float d1 = sqrtf(fmaxf(sqr[mi*2+0] + sqc1 - 2.f*acc[mi][j][1], 1e-12f));
      float d2 = sqrtf(fmaxf(sqr[mi*2+1] + sqc0 - 2.f*acc[mi][j][2], 1e-12f));
      float d3 = sqrtf(fmaxf(sqr[mi*2+1] + sqc1 - 2.f*acc[mi][j][3], 1e-12f));
      rsum[mi*2+0] += d0 + d1;
      rsum[mi*2+1] += d2 + d3;
      csum[j*2+0]  += d0 + d2;
      csum[j*2+1]  += d1 + d3;
    }
  }

  #pragma unroll
  for (int i=0;i<4;i++){
    rsum[i] += __shfl_xor_sync(0xffffffffu, rsum[i], 1);
    rsum[i] += __shfl_xor_sync(0xffffffffu, rsum[i], 2);
  }
  if ((lane & 3) == 0){
    #pragma unroll
    for (int mi=0;mi<2;mi++)
      #pragma unroll
      for (int h=0;h<2;h++)
        atomicAdd(&g_s[r0 + wm*32 + mi*16 + (lane>>2) + h*8], rsum[mi*2+h]);
  }

  if (!diag){
    #pragma unroll
    for (int i=0;i<8;i++){
      csum[i] += __shfl_xor_sync(0xffffffffu, csum[i], 4);
      csum[i] += __shfl_xor_sync(0xffffffffu, csum[i], 8);
      csum[i] += __shfl_xor_sync(0xffffffffu, csum[i], 16);
    }
    if ((lane >> 2) == 0){
      #pragma unroll
      for (int j=0;j<4;j++){
        int colg = c0 + wn*32 + j*8 + 2*(lane&3);
        atomicAdd(&g_s[colg],   csum[j*2+0]);
        atomicAdd(&g_s[colg+1], csum[j*2+1]);
      }
    }
  }
}

// ---------------------------------------------------------------------------
// k_final: softmax over 512 unique scores + weighted sum; write w and f.
// ---------------------------------------------------------------------------
__global__ void __launch_bounds__(256) k_final(
    const int* __restrict__ pairs, float* __restrict__ out)
{
  __shared__ float ev[512];
  __shared__ float red[256];
  const int b = blockIdx.x, tid = threadIdx.x;
  const float scale = 1.f/(512.f*0.25f);
  float x0 = g_s[b*HALF + tid      ]*scale;
  float x1 = g_s[b*HALF + 256 + tid]*scale;

  red[tid] = fmaxf(x0,x1);
  __syncthreads();
  for (int o=128;o;o>>=1){ if(tid<o) red[tid]=fmaxf(red[tid],red[tid+o]); __syncthreads(); }
  float mx = red[0];
  __syncthreads();

  float e0 = expf(x0-mx), e1 = expf(x1-mx);
  ev[tid] = e0; ev[tid+256] = e1;
  red[tid] = e0+e1;
  __syncthreads();
  for (int o=128;o;o>>=1){ if(tid<o) red[tid]+=red[tid+o]; __syncthreads(); }
  float inv = 1.f/red[0];

  float* wout = out + NBATCH*EMB;
  {
    int p = b*HALF + tid;
    float wv = ev[tid]*inv*0.5f;
    wout[pairs[2*p]]   = wv;
    wout[pairs[2*p+1]] = wv;
    p = b*HALF + 256 + tid;
    wv = ev[tid+256]*inv*0.5f;
    wout[pairs[2*p]]   = wv;
    wout[pairs[2*p+1]] = wv;
  }

  const int col = tid & 127, part = tid >> 7;
  float fs = 0.f;
  for (int i = part*256; i < part*256+256; i++){
    size_t gi = (size_t)(b*HALF+i)*EMB + col;
    float zv = __bfloat162float(g_zh[gi]) + __bfloat162float(g_zl[gi]);
    fs += ev[i]*inv * zv;
  }
  __syncthreads();
  red[tid] = fs;
  __syncthreads();
  if (tid < 128) out[b*EMB + tid] = red[tid] + red[tid+128];
}

// ---------------------------------------------------------------------------
extern "C" void kernel_launch(void* const* d_in, const int* in_sizes, int n_in,
                              void* d_out, int out_size)
{
  const float* H     = (const float*)d_in[0];
  const int*   pairs = (const int*)  d_in[2];
  const float* W_in  = (const float*)d_in[3];
  const float* b_in  = (const float*)d_in[4];
  const float* Wb    = (const float*)d_in[5];
  const float* bb    = (const float*)d_in[6];
  const float* lng   = (const float*)d_in[7];
  const float* lnb   = (const float*)d_in[8];
  const float* W_out = (const float*)d_in[9];
  const float* b_out = (const float*)d_in[10];
  const float* lnf_g = (const float*)d_in[11];
  const float* lnf_b = (const float*)d_in[12];
  float* out = (float*)d_out;

  cudaFuncSetAttribute(k_mega,     cudaFuncAttributeMaxDynamicSharedMemorySize, MEGA_SMEM);
  cudaFuncSetAttribute(k_gram_mma, cudaFuncAttributeMaxDynamicSharedMemorySize, GRM_SMEM);

  k_prep<<<(WT_TOTAL + 255)/256, 256>>>(Wb, W_out, W_in);
  k_mega<<<MROWS/128, 512, MEGA_SMEM>>>(H, pairs, b_in, bb, lng, lnb,
                                        b_out, lnf_g, lnf_b);
  k_gram_mma<<<dim3(36, NBATCH), 128, GRM_SMEM>>>();
  k_final<<<NBATCH, 256>>>(pairs, out);
}

// round 6
// speedup vs baseline: 3.1998x; 1.0606x over previous
#include <cuda_runtime.h>
#include <cuda_bf16.h>
#include <math.h>
#include <stdint.h>

#define NBATCH 64
#define HALF   512
#define INDIM  64
#define HID    256
#define EMB    128
#define MROWS  (NBATCH*HALF)   // 32768 unique rows
#define LN_EPS 1e-5f

// weight regions inside g_bt_*
#define WOUT_OFS (3*HID*HID)
#define WIN_OFS  (3*HID*HID + EMB*HID)
#define WT_TOTAL (WIN_OFS + HID*INDIM)

// ---------------- device scratch (allocation is forbidden) ------------------
__device__ __align__(16) __nv_bfloat16 g_bt_hi[WT_TOTAL];
__device__ __align__(16) __nv_bfloat16 g_bt_lo[WT_TOTAL];
__device__ __align__(16) __nv_bfloat16 g_zh[MROWS*EMB];   // z hi
__device__ __align__(16) __nv_bfloat16 g_zl[MROWS*EMB];   // z lo
__device__ float g_sq[MROWS];
__device__ float g_s [MROWS];
__device__ float g_w [MROWS];   // normalized softmax weights (unique rows)

// ---------------- helpers ----------------------------------------------------
__device__ __forceinline__ uint32_t smem_u32(const void* p){
  uint32_t a;
  asm("{ .reg .u64 t; cvta.to.shared.u64 t, %1; cvt.u32.u64 %0, t; }" : "=r"(a) : "l"(p));
  return a;
}
__device__ __forceinline__ void cp16(uint32_t dst, const void* src){
  asm volatile("cp.async.cg.shared.global [%0], [%1], 16;\n" :: "r"(dst), "l"(src));
}
#define CP_COMMIT() asm volatile("cp.async.commit_group;\n" ::: "memory")
#define CP_WAIT(n)  asm volatile("cp.async.wait_group %0;\n" :: "n"(n) : "memory")

__device__ __forceinline__ void ldsm4(uint32_t (&r)[4], uint32_t addr){
  asm volatile("ldmatrix.sync.aligned.m8n8.x4.shared.b16 {%0,%1,%2,%3}, [%4];\n"
    : "=r"(r[0]),"=r"(r[1]),"=r"(r[2]),"=r"(r[3]) : "r"(addr));
}
__device__ __forceinline__ void mma16816(float (&d)[4], const uint32_t (&a)[4],
                                         uint32_t b0, uint32_t b1){
  asm volatile("mma.sync.aligned.m16n8k16.row.col.f32.bf16.bf16.f32 "
    "{%0,%1,%2,%3}, {%4,%5,%6,%7}, {%8,%9}, {%0,%1,%2,%3};\n"
    : "+f"(d[0]),"+f"(d[1]),"+f"(d[2]),"+f"(d[3])
    : "r"(a[0]),"r"(a[1]),"r"(a[2]),"r"(a[3]), "r"(b0),"r"(b1));
}
// rows of 64B (32 bf16); 16B column-chunk c in 0..3; XOR swizzle
__device__ __forceinline__ uint32_t swz(int r, int c){
  return (uint32_t)(r*64 + ((c ^ ((r>>1)&3))<<4));
}
__device__ __forceinline__ void split_bf16(float x, __nv_bfloat16& h, __nv_bfloat16& l){
  h = __float2bfloat16(x);
  l = __float2bfloat16(x - __bfloat162float(h));
}
__device__ __forceinline__ void split2(float v0, float v1, uint32_t& whi, uint32_t& wlo){
  __nv_bfloat16 h0,l0,h1,l1;
  split_bf16(v0,h0,l0); split_bf16(v1,h1,l1);
  whi = ((uint32_t)__bfloat16_as_ushort(h1)<<16) | (uint32_t)__bfloat16_as_ushort(h0);
  wlo = ((uint32_t)__bfloat16_as_ushort(l1)<<16) | (uint32_t)__bfloat16_as_ushort(l0);
}
__device__ __forceinline__ float bf_lo(uint32_t w){
  return __bfloat162float(__ushort_as_bfloat16((unsigned short)(w & 0xffffu)));
}
__device__ __forceinline__ float bf_hi(uint32_t w){
  return __bfloat162float(__ushort_as_bfloat16((unsigned short)(w >> 16)));
}

// warp tile 32 rows x 64 cols, one k32 chunk, bf16x3 accumulate
__device__ __forceinline__ void warp_mma_chunk(
    float (&acc)[2][8][4],
    uint32_t aH, uint32_t aL, uint32_t bH, uint32_t bL,
    int wm, int wn, int lane)
{
  #pragma unroll
  for (int kk=0; kk<2; kk++){
    uint32_t ah[2][4], al[2][4];
    #pragma unroll
    for (int mi=0; mi<2; mi++){
      int row = wm*32 + mi*16 + (lane & 15);
      int c   = kk*2 + (lane >> 4);
      uint32_t off = swz(row, c);
      ldsm4(ah[mi], aH + off);
      ldsm4(al[mi], aL + off);
    }
    #pragma unroll
    for (int p=0; p<4; p++){
      int n = wn*64 + p*16 + ((lane>>4)<<3) + (lane & 7);
      int c = kk*2 + ((lane>>3)&1);
      uint32_t off = swz(n, c);
      uint32_t bh[4], bl[4];
      ldsm4(bh, bH + off);
      ldsm4(bl, bL + off);
      #pragma unroll
      for (int mi=0; mi<2; mi++){
        #pragma unroll
        for (int h=0; h<2; h++){
          mma16816(acc[mi][p*2+h], ah[mi], bh[2*h], bh[2*h+1]);
          mma16816(acc[mi][p*2+h], ah[mi], bl[2*h], bl[2*h+1]);
          mma16816(acc[mi][p*2+h], al[mi], bh[2*h], bh[2*h+1]);
        }
      }
    }
  }
}

// warp tile 32 rows x 32 cols, one k32 chunk, bf16x3
__device__ __forceinline__ void warp_mma_chunk32(
    float (&acc)[2][4][4],
    uint32_t aH, uint32_t aL, uint32_t bH, uint32_t bL,
    int wm, int wn, int lane)
{
  #pragma unroll
  for (int kk=0; kk<2; kk++){
    uint32_t ah[2][4], al[2][4];
    #pragma unroll
    for (int mi=0; mi<2; mi++){
      int row = wm*32 + mi*16 + (lane & 15);
      int c   = kk*2 + (lane >> 4);
      uint32_t off = swz(row, c);
      ldsm4(ah[mi], aH + off);
      ldsm4(al[mi], aL + off);
    }
    #pragma unroll
    for (int p=0; p<2; p++){
      int n = wn*32 + p*16 + ((lane>>4)<<3) + (lane & 7);
      int c = kk*2 + ((lane>>3)&1);
      uint32_t off = swz(n, c);
      uint32_t bh[4], bl[4];
      ldsm4(bh, bH + off);
      ldsm4(bl, bL + off);
      #pragma unroll
      for (int mi=0; mi<2; mi++){
        #pragma unroll
        for (int h=0; h<2; h++){
          mma16816(acc[mi][p*2+h], ah[mi], bh[2*h], bh[2*h+1]);
          mma16816(acc[mi][p*2+h], ah[mi], bl[2*h], bl[2*h+1]);
          mma16816(acc[mi][p*2+h], al[mi], bh[2*h], bh[2*h+1]);
        }
      }
    }
  }
}

// ---------------------------------------------------------------------------
// prep: transpose + hi/lo split of Wb, W_out, W_in; zero g_s
// ---------------------------------------------------------------------------
__global__ void __launch_bounds__(256) k_prep(
    const float* __restrict__ Wb, const float* __restrict__ Wout,
    const float* __restrict__ Win)
{
  int i = blockIdx.x*256 + threadIdx.x;
  if (i < MROWS) g_s[i] = 0.f;
  float v;
  if (i < WOUT_OFS){
    int layer = i >> 16;
    int n  = (i >> 8) & 255;
    int kk = i & 255;
    v = Wb[layer*HID*HID + kk*HID + n];
  } else if (i < WIN_OFS){
    int j = i - WOUT_OFS;
    int n  = j >> 8;
    int kk = j & 255;
    v = Wout[kk*EMB + n];
  } else if (i < WT_TOTAL){
    int j = i - WIN_OFS;
    int n  = j >> 6;
    int kk = j & 63;
    v = Win[kk*HID + n];
  } else return;
  __nv_bfloat16 h, l; split_bf16(v, h, l);
  g_bt_hi[i] = h; g_bt_lo[i] = l;
}

// ---------------------------------------------------------------------------
// k_mega: fused  delta -> GEMM_in -> 3x(residual LN block) -> GEMM_out+LN
// ---------------------------------------------------------------------------
#define HHI  0
#define HLO  65536
#define BST  131072
#define PRM  196608
#define PART 199680
#define IDX  203776
#define MEGA_SMEM 204800

__global__ void __launch_bounds__(512) k_mega(
    const float* __restrict__ H, const int* __restrict__ pairs,
    const float* __restrict__ b_in,
    const float* __restrict__ bb, const float* __restrict__ lng,
    const float* __restrict__ lnb,
    const float* __restrict__ bo, const float* __restrict__ lnf_g,
    const float* __restrict__ lnf_b)
{
  extern __shared__ char smem[];
  const uint32_t sb = smem_u32(smem);
  const int tid = threadIdx.x, lane = tid&31, wid = tid>>5;
  const int wm = wid>>2, wn = wid&3;
  const int row0 = blockIdx.x * 128;
  int*   li   = (int*)(smem + IDX);
  int*   ri   = li + 128;
  float* prm  = (float*)(smem + PRM);
  float* part = (float*)(smem + PART);

  if (tid < 128){
    li[tid] = pairs[2*(row0+tid)];
    ri[tid] = pairs[2*(row0+tid)+1];
  }
  if (tid < 256) prm[tid] = b_in[tid];
  __syncthreads();

  // ---- delta = |H[li]-H[ri]| into h planes 0,1 (K=64) ----
  #pragma unroll
  for (int u=0; u<2; u++){
    int e = tid + u*512;
    int r = e>>3, g = e&7;
    const float* pl = H + (size_t)li[r]*INDIM + g*8;
    const float* pr = H + (size_t)ri[r]*INDIM + g*8;
    float4 a0 = *(const float4*)pl,     a1 = *(const float4*)(pl+4);
    float4 b0 = *(const float4*)pr,     b1 = *(const float4*)(pr+4);
    float d0=fabsf(a0.x-b0.x), d1=fabsf(a0.y-b0.y), d2=fabsf(a0.z-b0.z), d3=fabsf(a0.w-b0.w);
    float d4=fabsf(a1.x-b1.x), d5=fabsf(a1.y-b1.y), d6=fabsf(a1.z-b1.z), d7=fabsf(a1.w-b1.w);
    uint32_t h0,h1,h2,h3,l0,l1,l2,l3;
    split2(d0,d1,h0,l0); split2(d2,d3,h1,l1);
    split2(d4,d5,h2,l2); split2(d6,d7,h3,l3);
    uint32_t off = (uint32_t)((g>>2)*8192) + swz(r, g&3);
    *(uint4*)(smem + HHI + off) = make_uint4(h0,h1,h2,h3);
    *(uint4*)(smem + HLO + off) = make_uint4(l0,l1,l2,l3);
  }

  auto loadB = [&](const __nv_bfloat16* BH, const __nv_bfloat16* BL,
                   int nrows, int kstride, int c, int s){
    uint32_t base = sb + BST + (uint32_t)s*32768;
    int iters = (nrows*4)/512;
    for (int u=0; u<iters; u++){
      int e = tid + u*512;
      int n = e>>2, q = e&3;
      size_t gi = (size_t)n*kstride + c*32 + q*8;
      uint32_t off = swz(n, q);
      cp16(base + off,         BH + gi);
      cp16(base + 16384 + off, BL + gi);
    }
    CP_COMMIT();
  };

  // ================= layer 0: h = delta @ W_in + b_in =================
  {
    const __nv_bfloat16* BH = g_bt_hi + WIN_OFS;
    const __nv_bfloat16* BL = g_bt_lo + WIN_OFS;
    loadB(BH, BL, 256, INDIM, 0, 0);
    loadB(BH, BL, 256, INDIM, 1, 1);
    float acc[2][8][4];
    #pragma unroll
    for (int mi=0;mi<2;mi++)
      #pragma unroll
      for (int j=0;j<8;j++)
        #pragma unroll
        for (int q=0;q<4;q++) acc[mi][j][q]=0.f;
    CP_WAIT(0);
    __syncthreads();
    warp_mma_chunk(acc, sb+HHI,      sb+HLO,      sb+BST,       sb+BST+16384,       wm, wn, lane);
    warp_mma_chunk(acc, sb+HHI+8192, sb+HLO+8192, sb+BST+32768, sb+BST+32768+16384, wm, wn, lane);
    __syncthreads();

    #pragma unroll
    for (int j=0;j<8;j++){
      int col = wn*64 + j*8 + 2*(lane&3);
      float b0 = prm[col], b1 = prm[col+1];
      int p = wn*2 + (j>>2), qj = j&3;
      #pragma unroll
      for (int mi=0;mi<2;mi++){
        #pragma unroll
        for (int h=0;h<2;h++){
          int rl = wm*32 + mi*16 + (lane>>2) + h*8;
          uint32_t adr = (uint32_t)p*8192 + swz(rl, qj) + 4*(lane&3);
          uint32_t whi, wlo;
          split2(acc[mi][j][h*2]+b0, acc[mi][j][h*2+1]+b1, whi, wlo);
          *(uint32_t*)(smem + HHI + adr) = whi;
          *(uint32_t*)(smem + HLO + adr) = wlo;
        }
      }
    }
    __syncthreads();
  }

  // ================= layers 1..3: h += relu(LN(h @ Wb + bb)) =================
  for (int L=0; L<3; L++){
    const __nv_bfloat16* BH = g_bt_hi + (size_t)L*HID*HID;
    const __nv_bfloat16* BL = g_bt_lo + (size_t)L*HID*HID;
    if (tid < 256){
      prm[tid]     = bb [L*HID+tid];
      prm[256+tid] = lng[L*HID+tid];
      prm[512+tid] = lnb[L*HID+tid];
    }
    loadB(BH, BL, 256, HID, 0, 0);
    loadB(BH, BL, 256, HID, 1, 1);

    float acc[2][8][4];
    #pragma unroll
    for (int mi=0;mi<2;mi++)
      #pragma unroll
      for (int j=0;j<8;j++)
        #pragma unroll
        for (int q=0;q<4;q++) acc[mi][j][q]=0.f;

    for (int c=0;c<8;c++){
      if (c<6) { CP_WAIT(1); } else { CP_WAIT(0); }
      __syncthreads();
      uint32_t bbase = sb + BST + (uint32_t)(c&1)*32768;
      warp_mma_chunk(acc, sb+HHI+(uint32_t)c*8192, sb+HLO+(uint32_t)c*8192,
                     bbase, bbase+16384, wm, wn, lane);
      __syncthreads();
      if (c<6) loadB(BH, BL, 256, HID, c+2, c&1);
    }

    float sum[4]={0.f,0.f,0.f,0.f}, ssq[4]={0.f,0.f,0.f,0.f};
    #pragma unroll
    for (int j=0;j<8;j++){
      int col = wn*64 + j*8 + 2*(lane&3);
      float b0 = prm[col], b1 = prm[col+1];
      #pragma unroll
      for (int mi=0;mi<2;mi++){
        acc[mi][j][0]+=b0; acc[mi][j][1]+=b1; acc[mi][j][2]+=b0; acc[mi][j][3]+=b1;
        sum[mi*2+0] += acc[mi][j][0]+acc[mi][j][1];
        ssq[mi*2+0] += acc[mi][j][0]*acc[mi][j][0]+acc[mi][j][1]*acc[mi][j][1];
        sum[mi*2+1] += acc[mi][j][2]+acc[mi][j][3];
        ssq[mi*2+1] += acc[mi][j][2]*acc[mi][j][2]+acc[mi][j][3]*acc[mi][j][3];
      }
    }
    #pragma unroll
    for (int s=0;s<4;s++){
      sum[s]+=__shfl_xor_sync(0xffffffffu,sum[s],1);
      sum[s]+=__shfl_xor_sync(0xffffffffu,sum[s],2);
      ssq[s]+=__shfl_xor_sync(0xffffffffu,ssq[s],1);
      ssq[s]+=__shfl_xor_sync(0xffffffffu,ssq[s],2);
    }
    if ((lane&3)==0){
      #pragma unroll
      for (int mi=0;mi<2;mi++)
        #pragma unroll
        for (int h=0;h<2;h++){
          int row = wm*32 + mi*16 + (lane>>2) + h*8;
          part[(row*4+wn)*2]   = sum[mi*2+h];
          part[(row*4+wn)*2+1] = ssq[mi*2+h];
        }
    }
    __syncthreads();
    float mu[4], rs[4];
    #pragma unroll
    for (int mi=0;mi<2;mi++)
      #pragma unroll
      for (int h=0;h<2;h++){
        int row = wm*32 + mi*16 + (lane>>2) + h*8;
        float s1 = part[(row*4+0)*2]+part[(row*4+1)*2]+part[(row*4+2)*2]+part[(row*4+3)*2];
        float s2 = part[(row*4+0)*2+1]+part[(row*4+1)*2+1]+part[(row*4+2)*2+1]+part[(row*4+3)*2+1];
        int s = mi*2+h;
        mu[s] = s1*(1.f/256.f);
        float var = s2*(1.f/256.f) - mu[s]*mu[s];
        rs[s] = rsqrtf(fmaxf(var,0.f) + LN_EPS);
      }
    #pragma unroll
    for (int j=0;j<8;j++){
      int col = wn*64 + j*8 + 2*(lane&3);
      float lg0 = prm[256+col], lg1 = prm[256+col+1];
      float lb0 = prm[512+col], lb1 = prm[512+col+1];
      int p = wn*2 + (j>>2), qj = j&3;
      #pragma unroll
      for (int mi=0;mi<2;mi++){
        #pragma unroll
        for (int h=0;h<2;h++){
          int rl = wm*32 + mi*16 + (lane>>2) + h*8;
          int s = mi*2+h;
          uint32_t adr = (uint32_t)p*8192 + swz(rl, qj) + 4*(lane&3);
          uint32_t ohh = *(uint32_t*)(smem + HHI + adr);
          uint32_t oll = *(uint32_t*)(smem + HLO + adr);
          float old0 = bf_lo(ohh) + bf_lo(oll);
          float old1 = bf_hi(ohh) + bf_hi(oll);
          float t0 = fmaxf((acc[mi][j][h*2]  -mu[s])*rs[s]*lg0 + lb0, 0.f);
          float t1 = fmaxf((acc[mi][j][h*2+1]-mu[s])*rs[s]*lg1 + lb1, 0.f);
          uint32_t whi, wlo;
          split2(old0+t0, old1+t1, whi, wlo);
          *(uint32_t*)(smem + HHI + adr) = whi;
          *(uint32_t*)(smem + HLO + adr) = wlo;
        }
      }
    }
    __syncthreads();
  }

  // ================= out layer: z = LN(h @ W_out + b_out), sq =================
  {
    const __nv_bfloat16* BH = g_bt_hi + WOUT_OFS;
    const __nv_bfloat16* BL = g_bt_lo + WOUT_OFS;
    if (tid < 128){
      prm[tid]     = bo[tid];
      prm[256+tid] = lnf_g[tid];
      prm[512+tid] = lnf_b[tid];
    }
    loadB(BH, BL, 128, HID, 0, 0);
    loadB(BH, BL, 128, HID, 1, 1);

    float acc[2][4][4];
    #pragma unroll
    for (int mi=0;mi<2;mi++)
      #pragma unroll
      for (int j=0;j<4;j++)
        #pragma unroll
        for (int q=0;q<4;q++) acc[mi][j][q]=0.f;

    for (int c=0;c<8;c++){
      if (c<6) { CP_WAIT(1); } else { CP_WAIT(0); }
      __syncthreads();
      uint32_t bbase = sb + BST + (uint32_t)(c&1)*32768;
      warp_mma_chunk32(acc, sb+HHI+(uint32_t)c*8192, sb+HLO+(uint32_t)c*8192,
                       bbase, bbase+16384, wm, wn, lane);
      __syncthreads();
      if (c<6) loadB(BH, BL, 128, HID, c+2, c&1);
    }

    float sum[4]={0.f,0.f,0.f,0.f}, ssq[4]={0.f,0.f,0.f,0.f};
    #pragma unroll
    for (int j=0;j<4;j++){
      int col = wn*32 + j*8 + 2*(lane&3);
      float b0 = prm[col], b1 = prm[col+1];
      #pragma unroll
      for (int mi=0;mi<2;mi++){
        acc[mi][j][0]+=b0; acc[mi][j][1]+=b1; acc[mi][j][2]+=b0; acc[mi][j][3]+=b1;
        sum[mi*2+0] += acc[mi][j][0]+acc[mi][j][1];
        ssq[mi*2+0] += acc[mi][j][0]*acc[mi][j][0]+acc[mi][j][1]*acc[mi][j][1];
        sum[mi*2+1] += acc[mi][j][2]+acc[mi][j][3];
        ssq[mi*2+1] += acc[mi][j][2]*acc[mi][j][2]+acc[mi][j][3]*acc[mi][j][3];
      }
    }
    #pragma unroll
    for (int s=0;s<4;s++){
      sum[s]+=__shfl_xor_sync(0xffffffffu,sum[s],1);
      sum[s]+=__shfl_xor_sync(0xffffffffu,sum[s],2);
      ssq[s]+=__shfl_xor_sync(0xffffffffu,ssq[s],1);
      ssq[s]+=__shfl_xor_sync(0xffffffffu,ssq[s],2);
    }
    if ((lane&3)==0){
      #pragma unroll
      for (int mi=0;mi<2;mi++)
        #pragma unroll
        for (int h=0;h<2;h++){
          int row = wm*32 + mi*16 + (lane>>2) + h*8;
          part[(row*4+wn)*2]   = sum[mi*2+h];
          part[(row*4+wn)*2+1] = ssq[mi*2+h];
        }
    }
    __syncthreads();
    float mu[4], rs[4];
    #pragma unroll
    for (int mi=0;mi<2;mi++)
      #pragma unroll
      for (int h=0;h<2;h++){
        int row = wm*32 + mi*16 + (lane>>2) + h*8;
        float s1 = part[(row*4+0)*2]+part[(row*4+1)*2]+part[(row*4+2)*2]+part[(row*4+3)*2];
        float s2 = part[(row*4+0)*2+1]+part[(row*4+1)*2+1]+part[(row*4+2)*2+1]+part[(row*4+3)*2+1];
        int s = mi*2+h;
        mu[s] = s1*(1.f/128.f);
        float var = s2*(1.f/128.f) - mu[s]*mu[s];
        rs[s] = rsqrtf(fmaxf(var,0.f) + LN_EPS);
      }
    float qs[4]={0.f,0.f,0.f,0.f};
    #pragma unroll
    for (int j=0;j<4;j++){
      int col = wn*32 + j*8 + 2*(lane&3);
      float lg0 = prm[256+col], lg1 = prm[256+col+1];
      float lb0 = prm[512+col], lb1 = prm[512+col+1];
      #pragma unroll
      for (int mi=0;mi<2;mi++){
        #pragma unroll
        for (int h=0;h<2;h++){
          int rl = wm*32 + mi*16 + (lane>>2) + h*8;
          int s = mi*2+h;
          float t0 = (acc[mi][j][h*2]  -mu[s])*rs[s]*lg0 + lb0;
          float t1 = (acc[mi][j][h*2+1]-mu[s])*rs[s]*lg1 + lb1;
          qs[s] += t0*t0 + t1*t1;
          uint32_t whi, wlo;
          split2(t0, t1, whi, wlo);
          size_t gi = (size_t)(row0+rl)*EMB + col;
          *(uint32_t*)(g_zh + gi) = whi;
          *(uint32_t*)(g_zl + gi) = wlo;
        }
      }
    }
    __syncthreads();
    #pragma unroll
    for (int s=0;s<4;s++){
      qs[s]+=__shfl_xor_sync(0xffffffffu,qs[s],1);
      qs[s]+=__shfl_xor_sync(0xffffffffu,qs[s],2);
    }
    if ((lane&3)==0){
      #pragma unroll
      for (int mi=0;mi<2;mi++)
        #pragma unroll
        for (int h=0;h<2;h++){
          int row = wm*32 + mi*16 + (lane>>2) + h*8;
          part[row*4+wn] = qs[mi*2+h];
        }
    }
    __syncthreads();
    if (wn==0 && (lane&3)==0){
      #pragma unroll
      for (int mi=0;mi<2;mi++)
        #pragma unroll
        for (int h=0;h<2;h++){
          int row = wm*32 + mi*16 + (lane>>2) + h*8;
          g_sq[row0+row] = part[row*4+0]+part[row*4+1]+part[row*4+2]+part[row*4+3];
        }
    }
  }
}

// ---------------------------------------------------------------------------
// k_gram_mma: per-batch 512x512 pairwise distances via symmetric 64x64 tiles.
// ---------------------------------------------------------------------------
#define GRM_SMEM 65536
__global__ void __launch_bounds__(128) k_gram_mma()
{
  extern __shared__ char smem[];
  const uint32_t sb = smem_u32(smem);
  const int tid = threadIdx.x, lane = tid&31, wid = tid>>5;
  const int wm = wid>>1, wn = wid&1;

  int t = blockIdx.x, rt = 0;
  while (t >= 8 - rt){ t -= 8 - rt; rt++; }
  const int ct = rt + t;
  const bool diag = (rt == ct);
  const int bofs = blockIdx.y * HALF;
  const int r0 = bofs + rt*64;
  const int c0 = bofs + ct*64;

  #pragma unroll
  for (int u=0; u<8; u++){
    int e = tid + u*128;
    int r = e>>4, tt = e&15;
    int c = tt>>2, q = tt&3;
    uint32_t off = (uint32_t)(c*4096) + swz(r, q);
    size_t gi = (size_t)(r0+r)*EMB + c*32 + q*8;
    cp16(sb + off,         g_zh + gi);
    cp16(sb + 16384 + off, g_zl + gi);
  }
  if (!diag){
    #pragma unroll
    for (int u=0; u<8; u++){
      int e = tid + u*128;
      int r = e>>4, tt = e&15;
      int c = tt>>2, q = tt&3;
      uint32_t off = (uint32_t)(c*4096) + swz(r, q);
      size_t gi = (size_t)(c0+r)*EMB + c*32 + q*8;
      cp16(sb + 32768 + off, g_zh + gi);
      cp16(sb + 49152 + off, g_zl + gi);
    }
  }
  CP_COMMIT(); CP_WAIT(0);
  __syncthreads();

  const uint32_t bHb = diag ? sb : (sb + 32768);
  const uint32_t bLb = diag ? (sb + 16384) : (sb + 49152);

  float acc[2][4][4];
  #pragma unroll
  for (int mi=0;mi<2;mi++)
    #pragma unroll
    for (int j=0;j<4;j++)
      #pragma unroll
      for (int q=0;q<4;q++) acc[mi][j][q]=0.f;

  #pragma unroll
  for (int c=0;c<4;c++)
    warp_mma_chunk32(acc, sb + c*4096, sb + 16384 + c*4096,
                     bHb + c*4096, bLb + c*4096, wm, wn, lane);

  float sqr[4];
  #pragma unroll
  for (int mi=0;mi<2;mi++)
    #pragma unroll
    for (int h=0;h<2;h++)
      sqr[mi*2+h] = g_sq[r0 + wm*32 + mi*16 + (lane>>2) + h*8];

  float rsum[4] = {0.f,0.f,0.f,0.f};
  float csum[8] = {0.f,0.f,0.f,0.f,0.f,0.f,0.f,0.f};
  #pragma unroll
  for (int j=0;j<4;j++){
    int colg = c0 + wn*32 + j*8 + 2*(lane&3);
    float sqc0 = g_sq[colg], sqc1 = g_sq[colg+1];
    #pragma unroll
    for (int mi=0;mi<2;mi++){
      float d0 = sqrtf(fmaxf(sqr[mi*2+0] + sqc0 - 2.f*acc[mi][j][0], 1e-12f));
      float d1 = sqrtf(fmaxf(sqr[mi*2+0] + sqc1 - 2.f*acc[mi][j][1], 1e-12f));
      float d2 = sqrtf(fmaxf(sqr[mi*2+1] + sqc0 - 2.f*acc[mi][j][2], 1e-12f));
      float d3 = sqrtf(fmaxf(sqr[mi*2+1] + sqc1 - 2.f*acc[mi][j][3], 1e-12f));
      rsum[mi*2+0] += d0 + d1;
      rsum[mi*2+1] += d2 + d3;
      csum[j*2+0]  += d0 + d2;
      csum[j*2+1]  += d1 + d3;
    }
  }

  #pragma unroll
  for (int i=0;i<4;i++){
    rsum[i] += __shfl_xor_sync(0xffffffffu, rsum[i], 1);
    rsum[i] += __shfl_xor_sync(0xffffffffu, rsum[i], 2);
  }
  if ((lane & 3) == 0){
    #pragma unroll
    for (int mi=0;mi<2;mi++)
      #pragma unroll
      for (int h=0;h<2;h++)
        atomicAdd(&g_s[r0 + wm*32 + mi*16 + (lane>>2) + h*8], rsum[mi*2+h]);
  }

  if (!diag){
    #pragma unroll
    for (int i=0;i<8;i++){
      csum[i] += __shfl_xor_sync(0xffffffffu, csum[i], 4);
      csum[i] += __shfl_xor_sync(0xffffffffu, csum[i], 8);
      csum[i] += __shfl_xor_sync(0xffffffffu, csum[i], 16);
    }
    if ((lane >> 2) == 0){
      #pragma unroll
      for (int j=0;j<4;j++){
        int colg = c0 + wn*32 + j*8 + 2*(lane&3);
        atomicAdd(&g_s[colg],   csum[j*2+0]);
        atomicAdd(&g_s[colg+1], csum[j*2+1]);
      }
    }
  }
}

// ---------------------------------------------------------------------------
// k_softmax: per batch softmax over 512 unique scores; write w output,
// normalized weights to g_w, and zero the f region of out.
// ---------------------------------------------------------------------------
__global__ void __launch_bounds__(256) k_softmax(
    const int* __restrict__ pairs, float* __restrict__ out)
{
  __shared__ float red[256];
  const int b = blockIdx.x, tid = threadIdx.x;
  const float scale = 1.f/(512.f*0.25f);
  float x0 = g_s[b*HALF + tid      ]*scale;
  float x1 = g_s[b*HALF + 256 + tid]*scale;

  red[tid] = fmaxf(x0,x1);
  __syncthreads();
  for (int o=128;o;o>>=1){ if(tid<o) red[tid]=fmaxf(red[tid],red[tid+o]); __syncthreads(); }
  float mx = red[0];
  __syncthreads();

  float e0 = expf(x0-mx), e1 = expf(x1-mx);
  red[tid] = e0+e1;
  __syncthreads();
  for (int o=128;o;o>>=1){ if(tid<o) red[tid]+=red[tid+o]; __syncthreads(); }
  float inv = 1.f/red[0];

  float w0 = e0*inv, w1 = e1*inv;
  g_w[b*HALF + tid]       = w0;
  g_w[b*HALF + 256 + tid] = w1;

  float* wout = out + NBATCH*EMB;
  {
    int p = b*HALF + tid;
    wout[pairs[2*p]]   = w0*0.5f;
    wout[pairs[2*p+1]] = w0*0.5f;
    p = b*HALF + 256 + tid;
    wout[pairs[2*p]]   = w1*0.5f;
    wout[pairs[2*p+1]] = w1*0.5f;
  }
  if (tid < EMB) out[b*EMB + tid] = 0.f;
}

// ---------------------------------------------------------------------------
// k_fsum: f[b] += sum over a 128-row slice of w[i] * z[i].  grid (4, NBATCH).
// Each thread owns a column pair (u32 loads) and a 32-row sub-slice.
// ---------------------------------------------------------------------------
__global__ void __launch_bounds__(256) k_fsum(float* __restrict__ out)
{
  __shared__ float wsh[128];
  __shared__ float red[512];
  const int b = blockIdx.y, tid = threadIdx.x;
  const int base = b*HALF + blockIdx.x*128;
  if (tid < 128) wsh[tid] = g_w[base + tid];
  __syncthreads();

  const int c2 = (tid & 63)*2;   // column pair
  const int p  = tid >> 6;       // 0..3 row sub-slice
  float f0 = 0.f, f1 = 0.f;
  #pragma unroll 4
  for (int r=0; r<32; r++){
    int ii = p*32 + r;
    float w = wsh[ii];
    size_t gi = (size_t)(base + ii)*EMB + c2;
    uint32_t zh = *(const uint32_t*)(g_zh + gi);
    uint32_t zl = *(const uint32_t*)(g_zl + gi);
    f0 = fmaf(w, bf_lo(zh) + bf_lo(zl), f0);
    f1 = fmaf(w, bf_hi(zh) + bf_hi(zl), f1);
  }
  red[tid*2]   = f0;
  red[tid*2+1] = f1;
  __syncthreads();
  if (tid < 64){
    float a0 = red[tid*2]   + red[(tid+64)*2]   + red[(tid+128)*2]   + red[(tid+192)*2];
    float a1 = red[tid*2+1] + red[(tid+64)*2+1] + red[(tid+128)*2+1] + red[(tid+192)*2+1];
    atomicAdd(&out[b*EMB + c2],   a0);
    atomicAdd(&out[b*EMB + c2+1], a1);
  }
}

// ---------------------------------------------------------------------------
extern "C" void kernel_launch(void* const* d_in, const int* in_sizes, int n_in,
                              void* d_out, int out_size)
{
  const float* H     = (const float*)d_in[0];
  const int*   pairs = (const int*)  d_in[2];
  const float* W_in  = (const float*)d_in[3];
  const float* b_in  = (const float*)d_in[4];
  const float* Wb    = (const float*)d_in[5];
  const float* bb    = (const float*)d_in[6];
  const float* lng   = (const float*)d_in[7];
  const float* lnb   = (const float*)d_in[8];
  const float* W_out = (const float*)d_in[9];
  const float* b_out = (const float*)d_in[10];
  const float* lnf_g = (const float*)d_in[11];
  const float* lnf_b = (const float*)d_in[12];
  float* out = (float*)d_out;

  cudaFuncSetAttribute(k_mega,     cudaFuncAttributeMaxDynamicSharedMemorySize, MEGA_SMEM);
  cudaFuncSetAttribute(k_gram_mma, cudaFuncAttributeMaxDynamicSharedMemorySize, GRM_SMEM);

  k_prep<<<(WT_TOTAL + 255)/256, 256>>>(Wb, W_out, W_in);
  k_mega<<<MROWS/128, 512, MEGA_SMEM>>>(H, pairs, b_in, bb, lng, lnb,
                                        b_out, lnf_g, lnf_b);
  k_gram_mma<<<dim3(36, NBATCH), 128, GRM_SMEM>>>();
  k_softmax<<<NBATCH, 256>>>(pairs, out);
  k_fsum<<<dim3(4, NBATCH), 256>>>(out);
}